// round 2
// baseline (speedup 1.0000x reference)
#include <cuda_runtime.h>
#include <math.h>

// Problem shape (fixed by the dataset): N = M = 4096, D = 256, K = 256.
#define NMAX 4096
#define DK   256
#define KTOP 256
#define CAP  16384

// ------------------------- device scratch (no allocs allowed) ---------------
__device__ float g_ms[(size_t)NMAX * NMAX];     // exp(2*dot - 2), row-major [N, M]  (64 MB)
__device__ float g_row[NMAX];
__device__ float g_col[NMAX];
__device__ float g_rowinv[NMAX];
__device__ float g_colinv[NMAX];
__device__ float g_colpart[32][NMAX];
__device__ unsigned int g_hist1[4096];
__device__ unsigned int g_hist2[4096];
__device__ unsigned int g_b1;
__device__ unsigned int g_cntAbove1;
__device__ unsigned int g_thresh;
__device__ unsigned int g_candCount;
__device__ unsigned long long g_cand[CAP];

// bit-exact score used identically in hist1 / hist2 / compact passes
__device__ __forceinline__ float score_val(float ms, float ri, float ci) {
    return __fmul_rn(__fmul_rn(ms, ri), __fmul_rn(ms, ci));
}

// ------------------------- zero mutable state (graph-replay idempotence) ----
__global__ void k_zero() {
    int t = blockIdx.x * blockDim.x + threadIdx.x;
    if (t < 4096) { g_hist1[t] = 0; g_hist2[t] = 0; }
    if (t == 0) { g_candCount = 0; g_b1 = 0; g_cntAbove1 = 0; g_thresh = 0; }
}

// ------------------------- fused GEMM + exp ---------------------------------
// C[i][j] = exp(2*dot(ref_i, src_j) - 2), 64x64 tile per block, 256 threads,
// 4x4 micro-tile per thread, k-chunk of 16.
__global__ void k_gemm_exp(const float* __restrict__ A, const float* __restrict__ B,
                           int N, int M, int D) {
    __shared__ float As[16][64];
    __shared__ float Bs[16][64];
    const int tid = threadIdx.x;
    const int tx = tid & 15;        // 0..15  -> 4 columns each
    const int ty = tid >> 4;        // 0..15  -> 4 rows each
    const int lr = tid >> 2;        // 0..63  load row within tile
    const int lk = (tid & 3) * 4;   // 0,4,8,12 load k offset
    const int i0 = blockIdx.y * 64;
    const int j0 = blockIdx.x * 64;

    float acc[4][4] = {};

    const float* Ap = A + (size_t)(i0 + lr) * D + lk;
    const float* Bp = B + (size_t)(j0 + lr) * D + lk;

    for (int kk = 0; kk < D; kk += 16) {
        float4 a4 = *(const float4*)(Ap + kk);
        float4 b4 = *(const float4*)(Bp + kk);
        __syncthreads();
        As[lk + 0][lr] = a4.x; As[lk + 1][lr] = a4.y;
        As[lk + 2][lr] = a4.z; As[lk + 3][lr] = a4.w;
        Bs[lk + 0][lr] = b4.x; Bs[lk + 1][lr] = b4.y;
        Bs[lk + 2][lr] = b4.z; Bs[lk + 3][lr] = b4.w;
        __syncthreads();
#pragma unroll
        for (int k = 0; k < 16; k++) {
            float4 av = *(const float4*)&As[k][ty * 4];
            float4 bv = *(const float4*)&Bs[k][tx * 4];
            acc[0][0] += av.x * bv.x; acc[0][1] += av.x * bv.y;
            acc[0][2] += av.x * bv.z; acc[0][3] += av.x * bv.w;
            acc[1][0] += av.y * bv.x; acc[1][1] += av.y * bv.y;
            acc[1][2] += av.y * bv.z; acc[1][3] += av.y * bv.w;
            acc[2][0] += av.z * bv.x; acc[2][1] += av.z * bv.y;
            acc[2][2] += av.z * bv.z; acc[2][3] += av.z * bv.w;
            acc[3][0] += av.w * bv.x; acc[3][1] += av.w * bv.y;
            acc[3][2] += av.w * bv.z; acc[3][3] += av.w * bv.w;
        }
    }

#pragma unroll
    for (int m = 0; m < 4; m++) {
        float4 o;
        o.x = expf(fmaf(2.0f, acc[m][0], -2.0f));
        o.y = expf(fmaf(2.0f, acc[m][1], -2.0f));
        o.z = expf(fmaf(2.0f, acc[m][2], -2.0f));
        o.w = expf(fmaf(2.0f, acc[m][3], -2.0f));
        *(float4*)&g_ms[(size_t)(i0 + ty * 4 + m) * M + j0 + tx * 4] = o;
    }
}

// ------------------------- deterministic row sums ---------------------------
__global__ void k_rowsum(int M) {
    const int row = blockIdx.x;
    const float4* p = (const float4*)&g_ms[(size_t)row * M];
    float s = 0.0f;
    for (int c = threadIdx.x; c < M / 4; c += 256) {
        float4 v = p[c];
        s += v.x + v.y + v.z + v.w;
    }
    __shared__ float sh[256];
    sh[threadIdx.x] = s;
    __syncthreads();
    for (int st = 128; st > 0; st >>= 1) {
        if (threadIdx.x < st) sh[threadIdx.x] += sh[threadIdx.x + st];
        __syncthreads();
    }
    if (threadIdx.x == 0) g_row[row] = sh[0];
}

// ------------------------- deterministic col sums (2-stage) -----------------
__global__ void k_colsumA(int N, int M) {
    const int col = blockIdx.x * 256 + threadIdx.x;
    const int rc  = blockIdx.y;               // 0..31
    const int rows = N / 32;
    const int r0 = rc * rows;
    float s = 0.0f;
    for (int r = r0; r < r0 + rows; r++) s += g_ms[(size_t)r * M + col];
    g_colpart[rc][col] = s;
}

__global__ void k_colsumB(int M) {
    const int col = blockIdx.x * 256 + threadIdx.x;
    float s = 0.0f;
#pragma unroll
    for (int p = 0; p < 32; p++) s += g_colpart[p][col];
    g_col[col] = s;
}

__global__ void k_invert(int N, int M) {
    int t = blockIdx.x * blockDim.x + threadIdx.x;
    if (t < N) g_rowinv[t] = 1.0f / g_row[t];
    else if (t < N + M) g_colinv[t - N] = 1.0f / g_col[t - N];
}

// ------------------------- radix-select pass 1 ------------------------------
// histogram of top 12 bits of the positive-float score
__global__ void k_score_hist1(int N, int M) {
    __shared__ unsigned int h[4096];
    for (int t = threadIdx.x; t < 4096; t += blockDim.x) h[t] = 0;
    __syncthreads();
    const int i0 = blockIdx.x * 8;
    for (int r = 0; r < 8; r++) {
        const int i = i0 + r;
        const float ri = g_rowinv[i];
        const float4* row = (const float4*)&g_ms[(size_t)i * M];
        const float4* cin = (const float4*)g_colinv;
        for (int j = threadIdx.x; j < M / 4; j += blockDim.x) {
            float4 ms = row[j];
            float4 ci = cin[j];
            atomicAdd(&h[__float_as_uint(score_val(ms.x, ri, ci.x)) >> 20], 1u);
            atomicAdd(&h[__float_as_uint(score_val(ms.y, ri, ci.y)) >> 20], 1u);
            atomicAdd(&h[__float_as_uint(score_val(ms.z, ri, ci.z)) >> 20], 1u);
            atomicAdd(&h[__float_as_uint(score_val(ms.w, ri, ci.w)) >> 20], 1u);
        }
    }
    __syncthreads();
    for (int t = threadIdx.x; t < 4096; t += blockDim.x) {
        unsigned int c = h[t];
        if (c) atomicAdd(&g_hist1[t], c);
    }
}

__global__ void k_findb1() {
    unsigned int cum = 0;
    int b;
    for (b = 4095; b >= 0; b--) {
        unsigned int c = g_hist1[b];
        if (cum + c >= KTOP) break;
        cum += c;
    }
    if (b < 0) b = 0;
    g_b1 = (unsigned int)b;
    g_cntAbove1 = cum;       // elements strictly above bin b1  (< KTOP)
}

// ------------------------- radix-select pass 2 (refine boundary bin) --------
__global__ void k_hist2(int N, int M) {
    const unsigned int b1 = g_b1;
    const int i0 = blockIdx.x * 8;
    for (int r = 0; r < 8; r++) {
        const int i = i0 + r;
        const float ri = g_rowinv[i];
        const float4* row = (const float4*)&g_ms[(size_t)i * M];
        const float4* cin = (const float4*)g_colinv;
        for (int j = threadIdx.x; j < M / 4; j += blockDim.x) {
            float4 ms = row[j];
            float4 ci = cin[j];
            unsigned int u;
            u = __float_as_uint(score_val(ms.x, ri, ci.x));
            if ((u >> 20) == b1) atomicAdd(&g_hist2[(u >> 8) & 0xFFF], 1u);
            u = __float_as_uint(score_val(ms.y, ri, ci.y));
            if ((u >> 20) == b1) atomicAdd(&g_hist2[(u >> 8) & 0xFFF], 1u);
            u = __float_as_uint(score_val(ms.z, ri, ci.z));
            if ((u >> 20) == b1) atomicAdd(&g_hist2[(u >> 8) & 0xFFF], 1u);
            u = __float_as_uint(score_val(ms.w, ri, ci.w));
            if ((u >> 20) == b1) atomicAdd(&g_hist2[(u >> 8) & 0xFFF], 1u);
        }
    }
}

__global__ void k_findb2() {
    unsigned int cum = g_cntAbove1;
    int b;
    for (b = 4095; b >= 0; b--) {
        unsigned int c = g_hist2[b];
        if (cum + c >= KTOP) break;
        cum += c;
    }
    if (b < 0) b = 0;
    g_thresh = (g_b1 << 20) | ((unsigned int)b << 8);
}

// ------------------------- compaction ---------------------------------------
__global__ void k_compact(int N, int M) {
    const unsigned int T = g_thresh;
    const int i0 = blockIdx.x * 8;
    for (int r = 0; r < 8; r++) {
        const int i = i0 + r;
        const float ri = g_rowinv[i];
        const float4* row = (const float4*)&g_ms[(size_t)i * M];
        const float4* cin = (const float4*)g_colinv;
        const unsigned int ebase = (unsigned int)i * (unsigned int)M;
        for (int j = threadIdx.x; j < M / 4; j += blockDim.x) {
            float4 ms = row[j];
            float4 ci = cin[j];
            float v[4];
            v[0] = score_val(ms.x, ri, ci.x);
            v[1] = score_val(ms.y, ri, ci.y);
            v[2] = score_val(ms.z, ri, ci.z);
            v[3] = score_val(ms.w, ri, ci.w);
#pragma unroll
            for (int c = 0; c < 4; c++) {
                unsigned int u = __float_as_uint(v[c]);
                if (u >= T) {
                    unsigned int pos = atomicAdd(&g_candCount, 1u);
                    if (pos < CAP) {
                        unsigned int e = ebase + (unsigned int)(j * 4 + c);
                        // key sorts by (value desc, flat index asc)
                        g_cand[pos] = ((unsigned long long)u << 32)
                                    | (unsigned long long)(0xFFFFFFFFu - e);
                    }
                }
            }
        }
    }
}

// ------------------------- final rank-sort + output -------------------------
__global__ void k_final(float* __restrict__ out, int M) {
    const int C = (int)min(g_candCount, (unsigned int)CAP);
    for (int c = threadIdx.x; c < C; c += blockDim.x) {
        const unsigned long long key = g_cand[c];
        int r = 0;
        for (int o = 0; o < C; o++) r += (g_cand[o] > key);
        if (r < KTOP) {
            unsigned int u   = (unsigned int)(key >> 32);
            unsigned int idx = 0xFFFFFFFFu - (unsigned int)(key & 0xFFFFFFFFu);
            out[r]            = (float)(idx / (unsigned int)M);   // ref index
            out[KTOP + r]     = (float)(idx % (unsigned int)M);   // src index
            out[2 * KTOP + r] = __uint_as_float(u);               // score
        }
    }
}

// ------------------------- launch -------------------------------------------
extern "C" void kernel_launch(void* const* d_in, const int* in_sizes, int n_in,
                              void* d_out, int out_size) {
    const float* ref = (const float*)d_in[0];
    const float* src = (const float*)d_in[1];
    const int D = DK;
    const int N = in_sizes[0] / D;
    const int M = in_sizes[1] / D;
    float* out = (float*)d_out;

    k_zero<<<16, 256>>>();

    dim3 gg(M / 64, N / 64);
    k_gemm_exp<<<gg, 256>>>(ref, src, N, M, D);

    k_rowsum<<<N, 256>>>(M);
    k_colsumA<<<dim3(M / 256, 32), 256>>>(N, M);
    k_colsumB<<<M / 256, 256>>>(M);
    k_invert<<<(N + M + 255) / 256, 256>>>(N, M);

    k_score_hist1<<<N / 8, 256>>>(N, M);
    k_findb1<<<1, 1>>>();
    k_hist2<<<N / 8, 256>>>(N, M);
    k_findb2<<<1, 1>>>();
    k_compact<<<N / 8, 256>>>(N, M);
    k_final<<<1, 1024>>>(out, M);
}

// round 5
// speedup vs baseline: 1.0170x; 1.0170x over previous
#include <cuda_runtime.h>
#include <cuda_bf16.h>
#include <math.h>
#include <stdint.h>

// Problem shape (fixed by the dataset): N = M = 4096, D = 256, K = 256.
#define NMAX 4096
#define DK   256
#define KD2  1536         // extended K: 6-term split
#define KTOP 256
#define CAP  16384

// ------------------------- device scratch (no allocs allowed) ---------------
__device__ float g_ms[(size_t)NMAX * NMAX];     // exp(2*dot - 2), row-major [N, M]  (64 MB)
__device__ __nv_bfloat16 g_A2[(size_t)NMAX * KD2];
__device__ __nv_bfloat16 g_B2[(size_t)NMAX * KD2];
__device__ float g_row[NMAX];
__device__ float g_col[NMAX];
__device__ float g_rowinv[NMAX];
__device__ float g_colinv[NMAX];
__device__ float g_colpart[32][NMAX];
__device__ unsigned int g_hist1[4096];
__device__ unsigned int g_hist2[4096];
__device__ unsigned int g_b1;
__device__ unsigned int g_cntAbove1;
__device__ unsigned int g_thresh;
__device__ unsigned int g_candCount;
__device__ unsigned long long g_cand[CAP];

// bit-exact score used identically in hist1 / hist2 / compact passes
__device__ __forceinline__ float score_val(float ms, float ri, float ci) {
    return __fmul_rn(__fmul_rn(ms, ri), __fmul_rn(ms, ci));
}

__device__ __forceinline__ uint32_t smem_u32(const void* p) {
    uint32_t a;
    asm("{ .reg .u64 t; cvta.to.shared.u64 t, %1; cvt.u32.u64 %0, t; }" : "=r"(a) : "l"(p));
    return a;
}

// ------------------------- zero mutable state (graph-replay idempotence) ----
__global__ void k_zero() {
    int t = blockIdx.x * blockDim.x + threadIdx.x;
    if (t < 4096) { g_hist1[t] = 0; g_hist2[t] = 0; }
    if (t == 0) { g_candCount = 0; g_b1 = 0; g_cntAbove1 = 0; g_thresh = 0; }
}

// ------------------------- fp32 -> 3-way bf16 split (6-term GEMM) -----------
// a = ah + am + al (each ~8 mantissa bits).
// A2 row = [ah|ah|ah|am|am|al],  B2 row = [bh|bm|bl|bh|bm|bh]
// dot(A2,B2) = ah*b(h+m+l) + am*(bh+bm) + al*bh ; dropped terms <= 2^-27 |ab|.
__global__ void k_split(const float* __restrict__ A, const float* __restrict__ B) {
    int idx = blockIdx.x * blockDim.x + threadIdx.x;     // 0 .. 4096*256-1
    int row = idx >> 8;          // /256
    int c   = idx & 255;
    size_t base = (size_t)row * KD2;

    float a = A[idx];
    __nv_bfloat16 ah = __float2bfloat16(a);
    float r1 = a - __bfloat162float(ah);
    __nv_bfloat16 am = __float2bfloat16(r1);
    __nv_bfloat16 al = __float2bfloat16(r1 - __bfloat162float(am));
    g_A2[base + c]         = ah;
    g_A2[base + 256 + c]   = ah;
    g_A2[base + 512 + c]   = ah;
    g_A2[base + 768 + c]   = am;
    g_A2[base + 1024 + c]  = am;
    g_A2[base + 1280 + c]  = al;

    float b = B[idx];
    __nv_bfloat16 bh = __float2bfloat16(b);
    float s1 = b - __bfloat162float(bh);
    __nv_bfloat16 bm = __float2bfloat16(s1);
    __nv_bfloat16 bl = __float2bfloat16(s1 - __bfloat162float(bm));
    g_B2[base + c]         = bh;
    g_B2[base + 256 + c]   = bm;
    g_B2[base + 512 + c]   = bl;
    g_B2[base + 768 + c]   = bh;
    g_B2[base + 1024 + c]  = bm;
    g_B2[base + 1280 + c]  = bh;
}

// ------------------------- HMMA bf16 GEMM + exp -----------------------------
// C = exp(2*A2·B2^T - 2).  CTA = 128x128 tile, 4 warps (64x64 each), k-step 16.
// Smem tiles padded to 24 elems/row (48B stride) -> conflict-free ldmatrix.
__global__ void __launch_bounds__(128, 2) k_gemm_mma(int M) {
    __shared__ __nv_bfloat16 As[128][24];
    __shared__ __nv_bfloat16 Bs[128][24];

    const int tid  = threadIdx.x;
    const int lane = tid & 31;
    const int warp = tid >> 5;        // 0..3
    const int wr   = warp >> 1;       // warp row 0..1  (64 rows)
    const int wc   = warp & 1;        // warp col 0..1  (64 cols)
    const int i0   = blockIdx.y * 128;
    const int j0   = blockIdx.x * 128;

    float acc[4][8][4];
#pragma unroll
    for (int a = 0; a < 4; a++)
#pragma unroll
        for (int b = 0; b < 8; b++)
#pragma unroll
            for (int c = 0; c < 4; c++) acc[a][b][c] = 0.0f;

    // global load indexing: thread covers 2 half-rows per tile
    const int gr0 = tid >> 1;         // row for flat i=0
    const int gh0 = tid & 1;          // 8-col half
    const int gr1 = (128 + tid) >> 1;
    const int gh1 = (128 + tid) & 1;

    // ldmatrix source addresses (fixed across k iterations)
    uint32_t a_addr[4], b_addr[4];
    {
        int arow = wr * 64 + (lane & 15);
        int acol = (lane >> 4) * 8;
#pragma unroll
        for (int mi = 0; mi < 4; mi++)
            a_addr[mi] = smem_u32(&As[arow + mi * 16][acol]);
        int bn = wc * 64 + ((lane >> 4) * 8) + (lane & 7);
        int bk = ((lane >> 3) & 1) * 8;
#pragma unroll
        for (int ni = 0; ni < 4; ni++)
            b_addr[ni] = smem_u32(&Bs[bn + ni * 16][bk]);
    }

    const __nv_bfloat16* Abase = &g_A2[(size_t)i0 * KD2];
    const __nv_bfloat16* Bbase = &g_B2[(size_t)j0 * KD2];

    for (int kc = 0; kc < KD2; kc += 16) {
        __syncthreads();
        {
            uint4 va0 = *(const uint4*)(Abase + (size_t)gr0 * KD2 + kc + gh0 * 8);
            uint4 va1 = *(const uint4*)(Abase + (size_t)gr1 * KD2 + kc + gh1 * 8);
            uint4 vb0 = *(const uint4*)(Bbase + (size_t)gr0 * KD2 + kc + gh0 * 8);
            uint4 vb1 = *(const uint4*)(Bbase + (size_t)gr1 * KD2 + kc + gh1 * 8);
            *(uint4*)&As[gr0][gh0 * 8] = va0;
            *(uint4*)&As[gr1][gh1 * 8] = va1;
            *(uint4*)&Bs[gr0][gh0 * 8] = vb0;
            *(uint4*)&Bs[gr1][gh1 * 8] = vb1;
        }
        __syncthreads();

        uint32_t af[4][4], bf[4][4];
#pragma unroll
        for (int mi = 0; mi < 4; mi++)
            asm volatile("ldmatrix.sync.aligned.m8n8.x4.shared.b16 {%0,%1,%2,%3}, [%4];"
                         : "=r"(af[mi][0]), "=r"(af[mi][1]), "=r"(af[mi][2]), "=r"(af[mi][3])
                         : "r"(a_addr[mi]));
#pragma unroll
        for (int ni = 0; ni < 4; ni++)
            asm volatile("ldmatrix.sync.aligned.m8n8.x4.shared.b16 {%0,%1,%2,%3}, [%4];"
                         : "=r"(bf[ni][0]), "=r"(bf[ni][1]), "=r"(bf[ni][2]), "=r"(bf[ni][3])
                         : "r"(b_addr[ni]));
#pragma unroll
        for (int mi = 0; mi < 4; mi++)
#pragma unroll
            for (int nj = 0; nj < 8; nj++) {
                const uint32_t bb0 = bf[nj >> 1][(nj & 1) * 2];
                const uint32_t bb1 = bf[nj >> 1][(nj & 1) * 2 + 1];
                asm volatile(
                    "mma.sync.aligned.m16n8k16.row.col.f32.bf16.bf16.f32 "
                    "{%0,%1,%2,%3}, {%4,%5,%6,%7}, {%8,%9}, {%0,%1,%2,%3};"
                    : "+f"(acc[mi][nj][0]), "+f"(acc[mi][nj][1]),
                      "+f"(acc[mi][nj][2]), "+f"(acc[mi][nj][3])
                    : "r"(af[mi][0]), "r"(af[mi][1]), "r"(af[mi][2]), "r"(af[mi][3]),
                      "r"(bb0), "r"(bb1));
            }
    }

    // epilogue: exp(2x-2), write to g_ms
    const int erow = i0 + wr * 64 + (lane >> 2);
    const int ecol = j0 + wc * 64 + (lane & 3) * 2;
#pragma unroll
    for (int mi = 0; mi < 4; mi++) {
#pragma unroll
        for (int nj = 0; nj < 8; nj++) {
            float2 lo, hi;
            lo.x = expf(fmaf(2.0f, acc[mi][nj][0], -2.0f));
            lo.y = expf(fmaf(2.0f, acc[mi][nj][1], -2.0f));
            hi.x = expf(fmaf(2.0f, acc[mi][nj][2], -2.0f));
            hi.y = expf(fmaf(2.0f, acc[mi][nj][3], -2.0f));
            *(float2*)&g_ms[(size_t)(erow + mi * 16) * M + ecol + nj * 8]     = lo;
            *(float2*)&g_ms[(size_t)(erow + mi * 16 + 8) * M + ecol + nj * 8] = hi;
        }
    }
}

// ------------------------- deterministic row sums ---------------------------
__global__ void k_rowsum(int M) {
    const int row = blockIdx.x;
    const float4* p = (const float4*)&g_ms[(size_t)row * M];
    float s = 0.0f;
    for (int c = threadIdx.x; c < M / 4; c += 256) {
        float4 v = p[c];
        s += v.x + v.y + v.z + v.w;
    }
    __shared__ float sh[256];
    sh[threadIdx.x] = s;
    __syncthreads();
    for (int st = 128; st > 0; st >>= 1) {
        if (threadIdx.x < st) sh[threadIdx.x] += sh[threadIdx.x + st];
        __syncthreads();
    }
    if (threadIdx.x == 0) g_row[row] = sh[0];
}

// ------------------------- deterministic col sums (2-stage) -----------------
__global__ void k_colsumA(int N, int M) {
    const int col = blockIdx.x * 256 + threadIdx.x;
    const int rc  = blockIdx.y;               // 0..31
    const int rows = N / 32;
    const int r0 = rc * rows;
    float s = 0.0f;
    for (int r = r0; r < r0 + rows; r++) s += g_ms[(size_t)r * M + col];
    g_colpart[rc][col] = s;
}

__global__ void k_colsumB(int M) {
    const int col = blockIdx.x * 256 + threadIdx.x;
    float s = 0.0f;
#pragma unroll
    for (int p = 0; p < 32; p++) s += g_colpart[p][col];
    g_col[col] = s;
}

__global__ void k_invert(int N, int M) {
    int t = blockIdx.x * blockDim.x + threadIdx.x;
    if (t < N) g_rowinv[t] = 1.0f / g_row[t];
    else if (t < N + M) g_colinv[t - N] = 1.0f / g_col[t - N];
}

// ------------------------- radix-select pass 1 ------------------------------
__global__ void k_score_hist1(int N, int M) {
    __shared__ unsigned int h[4096];
    for (int t = threadIdx.x; t < 4096; t += blockDim.x) h[t] = 0;
    __syncthreads();
    const int i0 = blockIdx.x * 8;
    for (int r = 0; r < 8; r++) {
        const int i = i0 + r;
        const float ri = g_rowinv[i];
        const float4* row = (const float4*)&g_ms[(size_t)i * M];
        const float4* cin = (const float4*)g_colinv;
        for (int j = threadIdx.x; j < M / 4; j += blockDim.x) {
            float4 ms = row[j];
            float4 ci = cin[j];
            atomicAdd(&h[__float_as_uint(score_val(ms.x, ri, ci.x)) >> 20], 1u);
            atomicAdd(&h[__float_as_uint(score_val(ms.y, ri, ci.y)) >> 20], 1u);
            atomicAdd(&h[__float_as_uint(score_val(ms.z, ri, ci.z)) >> 20], 1u);
            atomicAdd(&h[__float_as_uint(score_val(ms.w, ri, ci.w)) >> 20], 1u);
        }
    }
    __syncthreads();
    for (int t = threadIdx.x; t < 4096; t += blockDim.x) {
        unsigned int c = h[t];
        if (c) atomicAdd(&g_hist1[t], c);
    }
}

__global__ void k_findb1() {
    unsigned int cum = 0;
    int b;
    for (b = 4095; b >= 0; b--) {
        unsigned int c = g_hist1[b];
        if (cum + c >= KTOP) break;
        cum += c;
    }
    if (b < 0) b = 0;
    g_b1 = (unsigned int)b;
    g_cntAbove1 = cum;
}

// ------------------------- radix-select pass 2 ------------------------------
__global__ void k_hist2(int N, int M) {
    const unsigned int b1 = g_b1;
    const int i0 = blockIdx.x * 8;
    for (int r = 0; r < 8; r++) {
        const int i = i0 + r;
        const float ri = g_rowinv[i];
        const float4* row = (const float4*)&g_ms[(size_t)i * M];
        const float4* cin = (const float4*)g_colinv;
        for (int j = threadIdx.x; j < M / 4; j += blockDim.x) {
            float4 ms = row[j];
            float4 ci = cin[j];
            unsigned int u;
            u = __float_as_uint(score_val(ms.x, ri, ci.x));
            if ((u >> 20) == b1) atomicAdd(&g_hist2[(u >> 8) & 0xFFF], 1u);
            u = __float_as_uint(score_val(ms.y, ri, ci.y));
            if ((u >> 20) == b1) atomicAdd(&g_hist2[(u >> 8) & 0xFFF], 1u);
            u = __float_as_uint(score_val(ms.z, ri, ci.z));
            if ((u >> 20) == b1) atomicAdd(&g_hist2[(u >> 8) & 0xFFF], 1u);
            u = __float_as_uint(score_val(ms.w, ri, ci.w));
            if ((u >> 20) == b1) atomicAdd(&g_hist2[(u >> 8) & 0xFFF], 1u);
        }
    }
}

__global__ void k_findb2() {
    unsigned int cum = g_cntAbove1;
    int b;
    for (b = 4095; b >= 0; b--) {
        unsigned int c = g_hist2[b];
        if (cum + c >= KTOP) break;
        cum += c;
    }
    if (b < 0) b = 0;
    g_thresh = (g_b1 << 20) | ((unsigned int)b << 8);
}

// ------------------------- compaction ---------------------------------------
__global__ void k_compact(int N, int M) {
    const unsigned int T = g_thresh;
    const int i0 = blockIdx.x * 8;
    for (int r = 0; r < 8; r++) {
        const int i = i0 + r;
        const float ri = g_rowinv[i];
        const float4* row = (const float4*)&g_ms[(size_t)i * M];
        const float4* cin = (const float4*)g_colinv;
        const unsigned int ebase = (unsigned int)i * (unsigned int)M;
        for (int j = threadIdx.x; j < M / 4; j += blockDim.x) {
            float4 ms = row[j];
            float4 ci = cin[j];
            float v[4];
            v[0] = score_val(ms.x, ri, ci.x);
            v[1] = score_val(ms.y, ri, ci.y);
            v[2] = score_val(ms.z, ri, ci.z);
            v[3] = score_val(ms.w, ri, ci.w);
#pragma unroll
            for (int c = 0; c < 4; c++) {
                unsigned int u = __float_as_uint(v[c]);
                if (u >= T) {
                    unsigned int pos = atomicAdd(&g_candCount, 1u);
                    if (pos < CAP) {
                        unsigned int e = ebase + (unsigned int)(j * 4 + c);
                        g_cand[pos] = ((unsigned long long)u << 32)
                                    | (unsigned long long)(0xFFFFFFFFu - e);
                    }
                }
            }
        }
    }
}

// ------------------------- final rank-sort + output -------------------------
__global__ void k_final(float* __restrict__ out, int M) {
    const int C = (int)min(g_candCount, (unsigned int)CAP);
    for (int c = threadIdx.x; c < C; c += blockDim.x) {
        const unsigned long long key = g_cand[c];
        int r = 0;
        for (int o = 0; o < C; o++) r += (g_cand[o] > key);
        if (r < KTOP) {
            unsigned int u   = (unsigned int)(key >> 32);
            unsigned int idx = 0xFFFFFFFFu - (unsigned int)(key & 0xFFFFFFFFu);
            out[r]            = (float)(idx / (unsigned int)M);   // ref index
            out[KTOP + r]     = (float)(idx % (unsigned int)M);   // src index
            out[2 * KTOP + r] = __uint_as_float(u);               // score
        }
    }
}

// ------------------------- launch -------------------------------------------
extern "C" void kernel_launch(void* const* d_in, const int* in_sizes, int n_in,
                              void* d_out, int out_size) {
    const float* ref = (const float*)d_in[0];
    const float* src = (const float*)d_in[1];
    const int D = DK;
    const int N = in_sizes[0] / D;
    const int M = in_sizes[1] / D;
    float* out = (float*)d_out;

    k_zero<<<16, 256>>>();
    k_split<<<(N * D) / 256, 256>>>(ref, src);

    dim3 gg(M / 128, N / 128);
    k_gemm_mma<<<gg, 128>>>(M);

    k_rowsum<<<N, 256>>>(M);
    k_colsumA<<<dim3(M / 256, 32), 256>>>(N, M);
    k_colsumB<<<M / 256, 256>>>(M);
    k_invert<<<(N + M + 255) / 256, 256>>>(N, M);

    k_score_hist1<<<N / 8, 256>>>(N, M);
    k_findb1<<<1, 1>>>();
    k_hist2<<<N / 8, 256>>>(N, M);
    k_findb2<<<1, 1>>>();
    k_compact<<<N / 8, 256>>>(N, M);
    k_final<<<1, 1024>>>(out, M);
}

// round 7
// speedup vs baseline: 2.2511x; 2.2134x over previous
#include <cuda_runtime.h>
#include <cuda_bf16.h>
#include <math.h>
#include <stdint.h>

// Problem shape (fixed by the dataset): N = M = 4096, D = 256, K = 256.
#define NMAX 4096
#define DK   256
#define KD2  1536         // extended K: 6-term split
#define KSTEPS 48         // KD2 / 32
#define KTOP 256
#define CAP  16384

// ------------------------- device scratch (no allocs allowed) ---------------
__device__ float g_ms[(size_t)NMAX * NMAX];     // exp(2*dot - 2), row-major [N, M]  (64 MB)
__device__ __nv_bfloat16 g_A2[(size_t)NMAX * KD2];
__device__ __nv_bfloat16 g_B2[(size_t)NMAX * KD2];
__device__ float g_row[NMAX];
__device__ float g_col[NMAX];
__device__ float g_rowinv[NMAX];
__device__ float g_colinv[NMAX];
__device__ float g_colpart[32][NMAX];
__device__ unsigned int g_hist1[4096];
__device__ unsigned int g_hist2[4096];
__device__ unsigned int g_b1;
__device__ unsigned int g_cntAbove1;
__device__ unsigned int g_thresh;
__device__ unsigned int g_candCount;
__device__ unsigned long long g_cand[CAP];

// bit-exact score used identically in hist1 / hist2 / compact passes
__device__ __forceinline__ float score_val(float ms, float ri, float ci) {
    return __fmul_rn(__fmul_rn(ms, ri), __fmul_rn(ms, ci));
}

__device__ __forceinline__ uint32_t smem_u32(const void* p) {
    uint32_t a;
    asm("{ .reg .u64 t; cvta.to.shared.u64 t, %1; cvt.u32.u64 %0, t; }" : "=r"(a) : "l"(p));
    return a;
}

// ------------------------- zero mutable state (graph-replay idempotence) ----
__global__ void k_zero() {
    int t = blockIdx.x * blockDim.x + threadIdx.x;
    if (t < 4096) { g_hist1[t] = 0; g_hist2[t] = 0; }
    if (t == 0) { g_candCount = 0; g_b1 = 0; g_cntAbove1 = 0; g_thresh = 0; }
}

// ------------------------- fp32 -> 3-way bf16 split (6-term GEMM) -----------
// a = ah + am + al.  A2 row = [ah|ah|ah|am|am|al],  B2 row = [bh|bm|bl|bh|bm|bh]
__global__ void k_split(const float* __restrict__ A, const float* __restrict__ B) {
    int idx = blockIdx.x * blockDim.x + threadIdx.x;     // 0 .. 4096*256-1
    int row = idx >> 8;
    int c   = idx & 255;
    size_t base = (size_t)row * KD2;

    float a = A[idx];
    __nv_bfloat16 ah = __float2bfloat16(a);
    float r1 = a - __bfloat162float(ah);
    __nv_bfloat16 am = __float2bfloat16(r1);
    __nv_bfloat16 al = __float2bfloat16(r1 - __bfloat162float(am));
    g_A2[base + c]         = ah;
    g_A2[base + 256 + c]   = ah;
    g_A2[base + 512 + c]   = ah;
    g_A2[base + 768 + c]   = am;
    g_A2[base + 1024 + c]  = am;
    g_A2[base + 1280 + c]  = al;

    float b = B[idx];
    __nv_bfloat16 bh = __float2bfloat16(b);
    float s1 = b - __bfloat162float(bh);
    __nv_bfloat16 bm = __float2bfloat16(s1);
    __nv_bfloat16 bl = __float2bfloat16(s1 - __bfloat162float(bm));
    g_B2[base + c]         = bh;
    g_B2[base + 256 + c]   = bm;
    g_B2[base + 512 + c]   = bl;
    g_B2[base + 768 + c]   = bh;
    g_B2[base + 1024 + c]  = bm;
    g_B2[base + 1280 + c]  = bh;
}

// ------------------------- HMMA bf16 GEMM + exp (double-buffered) -----------
// CTA = 128x128, 256 threads / 8 warps, warp tile 32x64, k-step 32, cp.async.
// Smem rows padded to 40 bf16 (80B) -> conflict-free ldmatrix.
__global__ void __launch_bounds__(256, 2) k_gemm_mma(int M) {
    __shared__ __nv_bfloat16 As[2][128][40];
    __shared__ __nv_bfloat16 Bs[2][128][40];

    const int tid  = threadIdx.x;
    const int lane = tid & 31;
    const int warp = tid >> 5;        // 0..7
    const int wr   = warp >> 1;       // 0..3  (32-row band)
    const int wc   = warp & 1;        // 0..1  (64-col band)
    const int i0   = blockIdx.y * 128;
    const int j0   = blockIdx.x * 128;

    float acc[2][8][4];
#pragma unroll
    for (int a = 0; a < 2; a++)
#pragma unroll
        for (int b = 0; b < 8; b++)
#pragma unroll
            for (int c = 0; c < 4; c++) acc[a][b][c] = 0.0f;

    const __nv_bfloat16* Abase = &g_A2[(size_t)i0 * KD2];
    const __nv_bfloat16* Bbase = &g_B2[(size_t)j0 * KD2];

    const uint32_t sA = smem_u32(&As[0][0][0]);
    const uint32_t sB = smem_u32(&Bs[0][0][0]);

    // cp.async indexing: 512 16B-chunks per (matrix, buffer); 2 per thread.
    const int ld_row0 = tid >> 2;             // chunk 0 row
    const int ld_seg0 = tid & 3;
    const int ld_row1 = (tid + 256) >> 2;     // chunk 1 row
    const int ld_seg1 = (tid + 256) & 3;

#define PREFETCH(buf, kc) do {                                                    \
    {                                                                             \
        const void* s0 = Abase + (size_t)ld_row0 * KD2 + (kc) * 32 + ld_seg0 * 8; \
        uint32_t d0 = sA + (((buf) * 128 + ld_row0) * 40 + ld_seg0 * 8) * 2;      \
        asm volatile("cp.async.cg.shared.global [%0], [%1], 16;" :: "r"(d0), "l"(s0)); \
        const void* s1 = Abase + (size_t)ld_row1 * KD2 + (kc) * 32 + ld_seg1 * 8; \
        uint32_t d1 = sA + (((buf) * 128 + ld_row1) * 40 + ld_seg1 * 8) * 2;      \
        asm volatile("cp.async.cg.shared.global [%0], [%1], 16;" :: "r"(d1), "l"(s1)); \
        const void* s2 = Bbase + (size_t)ld_row0 * KD2 + (kc) * 32 + ld_seg0 * 8; \
        uint32_t d2 = sB + (((buf) * 128 + ld_row0) * 40 + ld_seg0 * 8) * 2;      \
        asm volatile("cp.async.cg.shared.global [%0], [%1], 16;" :: "r"(d2), "l"(s2)); \
        const void* s3 = Bbase + (size_t)ld_row1 * KD2 + (kc) * 32 + ld_seg1 * 8; \
        uint32_t d3 = sB + (((buf) * 128 + ld_row1) * 40 + ld_seg1 * 8) * 2;      \
        asm volatile("cp.async.cg.shared.global [%0], [%1], 16;" :: "r"(d3), "l"(s3)); \
    }                                                                             \
    asm volatile("cp.async.commit_group;" ::: "memory");                          \
} while (0)

    // ldmatrix fixed per-thread offsets (elements)
    const int a_row  = wr * 32 + (lane & 15);
    const int a_col  = (lane >> 4) * 8;
    const int b_row  = wc * 64 + (lane >> 4) * 8 + (lane & 7);
    const int b_col  = ((lane >> 3) & 1) * 8;

    PREFETCH(0, 0);

    for (int kc = 0; kc < KSTEPS; kc++) {
        const int cur = kc & 1;
        if (kc + 1 < KSTEPS) {
            PREFETCH(cur ^ 1, kc + 1);
            asm volatile("cp.async.wait_group 1;" ::: "memory");
        } else {
            asm volatile("cp.async.wait_group 0;" ::: "memory");
        }
        __syncthreads();

#pragma unroll
        for (int h = 0; h < 2; h++) {
            uint32_t af[2][4], bfr[4][4];
#pragma unroll
            for (int mi = 0; mi < 2; mi++) {
                uint32_t addr = sA + (((cur * 128 + a_row + mi * 16) * 40) + a_col + 16 * h) * 2;
                asm volatile("ldmatrix.sync.aligned.m8n8.x4.shared.b16 {%0,%1,%2,%3}, [%4];"
                             : "=r"(af[mi][0]), "=r"(af[mi][1]), "=r"(af[mi][2]), "=r"(af[mi][3])
                             : "r"(addr));
            }
#pragma unroll
            for (int ni = 0; ni < 4; ni++) {
                uint32_t addr = sB + (((cur * 128 + b_row + ni * 16) * 40) + b_col + 16 * h) * 2;
                asm volatile("ldmatrix.sync.aligned.m8n8.x4.shared.b16 {%0,%1,%2,%3}, [%4];"
                             : "=r"(bfr[ni][0]), "=r"(bfr[ni][1]), "=r"(bfr[ni][2]), "=r"(bfr[ni][3])
                             : "r"(addr));
            }
#pragma unroll
            for (int mi = 0; mi < 2; mi++)
#pragma unroll
                for (int nj = 0; nj < 8; nj++) {
                    const uint32_t bb0 = bfr[nj >> 1][(nj & 1) * 2];
                    const uint32_t bb1 = bfr[nj >> 1][(nj & 1) * 2 + 1];
                    asm volatile(
                        "mma.sync.aligned.m16n8k16.row.col.f32.bf16.bf16.f32 "
                        "{%0,%1,%2,%3}, {%4,%5,%6,%7}, {%8,%9}, {%0,%1,%2,%3};"
                        : "+f"(acc[mi][nj][0]), "+f"(acc[mi][nj][1]),
                          "+f"(acc[mi][nj][2]), "+f"(acc[mi][nj][3])
                        : "r"(af[mi][0]), "r"(af[mi][1]), "r"(af[mi][2]), "r"(af[mi][3]),
                          "r"(bb0), "r"(bb1));
                }
        }
        __syncthreads();
    }
#undef PREFETCH

    // epilogue: exp(2x-2), write to g_ms
    const int erow = i0 + wr * 32 + (lane >> 2);
    const int ecol = j0 + wc * 64 + (lane & 3) * 2;
#pragma unroll
    for (int mi = 0; mi < 2; mi++) {
#pragma unroll
        for (int nj = 0; nj < 8; nj++) {
            float2 lo, hi;
            lo.x = expf(fmaf(2.0f, acc[mi][nj][0], -2.0f));
            lo.y = expf(fmaf(2.0f, acc[mi][nj][1], -2.0f));
            hi.x = expf(fmaf(2.0f, acc[mi][nj][2], -2.0f));
            hi.y = expf(fmaf(2.0f, acc[mi][nj][3], -2.0f));
            *(float2*)&g_ms[(size_t)(erow + mi * 16) * M + ecol + nj * 8]     = lo;
            *(float2*)&g_ms[(size_t)(erow + mi * 16 + 8) * M + ecol + nj * 8] = hi;
        }
    }
}

// ------------------------- deterministic row sums ---------------------------
__global__ void k_rowsum(int M) {
    const int row = blockIdx.x;
    const float4* p = (const float4*)&g_ms[(size_t)row * M];
    float s = 0.0f;
    for (int c = threadIdx.x; c < M / 4; c += 256) {
        float4 v = p[c];
        s += v.x + v.y + v.z + v.w;
    }
    __shared__ float sh[256];
    sh[threadIdx.x] = s;
    __syncthreads();
    for (int st = 128; st > 0; st >>= 1) {
        if (threadIdx.x < st) sh[threadIdx.x] += sh[threadIdx.x + st];
        __syncthreads();
    }
    if (threadIdx.x == 0) g_row[row] = sh[0];
}

// ------------------------- deterministic col sums (2-stage) -----------------
__global__ void k_colsumA(int N, int M) {
    const int col = blockIdx.x * 256 + threadIdx.x;
    const int rc  = blockIdx.y;               // 0..31
    const int rows = N / 32;
    const int r0 = rc * rows;
    float s = 0.0f;
    for (int r = r0; r < r0 + rows; r++) s += g_ms[(size_t)r * M + col];
    g_colpart[rc][col] = s;
}

__global__ void k_colsumB(int M) {
    const int col = blockIdx.x * 256 + threadIdx.x;
    float s = 0.0f;
#pragma unroll
    for (int p = 0; p < 32; p++) s += g_colpart[p][col];
    g_col[col] = s;
}

__global__ void k_invert(int N, int M) {
    int t = blockIdx.x * blockDim.x + threadIdx.x;
    if (t < N) g_rowinv[t] = 1.0f / g_row[t];
    else if (t < N + M) g_colinv[t - N] = 1.0f / g_col[t - N];
}

// ------------------------- radix-select pass 1 ------------------------------
// warp-aggregated histogram of top 12 bits (scores cluster -> heavy contention)
__device__ __forceinline__ void hist_add(unsigned int* h, unsigned int bin) {
    unsigned int mask = __match_any_sync(0xFFFFFFFFu, bin);
    unsigned int leader = __ffs(mask) - 1u;
    if ((threadIdx.x & 31) == leader) atomicAdd(&h[bin], __popc(mask));
}

__global__ void k_score_hist1(int N, int M) {
    __shared__ unsigned int h[4096];
    for (int t = threadIdx.x; t < 4096; t += blockDim.x) h[t] = 0;
    __syncthreads();
    const int i0 = blockIdx.x * 8;
    for (int r = 0; r < 8; r++) {
        const int i = i0 + r;
        const float ri = g_rowinv[i];
        const float4* row = (const float4*)&g_ms[(size_t)i * M];
        const float4* cin = (const float4*)g_colinv;
        for (int j = threadIdx.x; j < M / 4; j += blockDim.x) {
            float4 ms = row[j];
            float4 ci = cin[j];
            hist_add(h, __float_as_uint(score_val(ms.x, ri, ci.x)) >> 20);
            hist_add(h, __float_as_uint(score_val(ms.y, ri, ci.y)) >> 20);
            hist_add(h, __float_as_uint(score_val(ms.z, ri, ci.z)) >> 20);
            hist_add(h, __float_as_uint(score_val(ms.w, ri, ci.w)) >> 20);
        }
    }
    __syncthreads();
    for (int t = threadIdx.x; t < 4096; t += blockDim.x) {
        unsigned int c = h[t];
        if (c) atomicAdd(&g_hist1[t], c);
    }
}

// parallel boundary find: 256 threads chunk-sum, then short serial refine
__global__ void k_findb1() {
    __shared__ unsigned int s[256];
    const int t = threadIdx.x;
    unsigned int sum = 0;
    for (int b = t * 16; b < t * 16 + 16; b++) sum += g_hist1[b];
    s[t] = sum;
    __syncthreads();
    if (t == 0) {
        unsigned int cum = 0;
        int chunk = 0;
        for (int c = 255; c >= 0; c--) {
            if (cum + s[c] >= KTOP) { chunk = c; break; }
            cum += s[c];
            if (c == 0) chunk = 0;
        }
        int b;
        for (b = chunk * 16 + 15; b > chunk * 16; b--) {
            unsigned int c2 = g_hist1[b];
            if (cum + c2 >= KTOP) break;
            cum += c2;
        }
        g_b1 = (unsigned int)b;
        g_cntAbove1 = cum;
    }
}

// ------------------------- radix-select pass 2 ------------------------------
__global__ void k_hist2(int N, int M) {
    __shared__ unsigned int h[4096];
    for (int t = threadIdx.x; t < 4096; t += blockDim.x) h[t] = 0;
    __syncthreads();
    const unsigned int b1 = g_b1;
    const int i0 = blockIdx.x * 8;
    for (int r = 0; r < 8; r++) {
        const int i = i0 + r;
        const float ri = g_rowinv[i];
        const float4* row = (const float4*)&g_ms[(size_t)i * M];
        const float4* cin = (const float4*)g_colinv;
        for (int j = threadIdx.x; j < M / 4; j += blockDim.x) {
            float4 ms = row[j];
            float4 ci = cin[j];
            unsigned int u;
            u = __float_as_uint(score_val(ms.x, ri, ci.x));
            if ((u >> 20) == b1) atomicAdd(&h[(u >> 8) & 0xFFF], 1u);
            u = __float_as_uint(score_val(ms.y, ri, ci.y));
            if ((u >> 20) == b1) atomicAdd(&h[(u >> 8) & 0xFFF], 1u);
            u = __float_as_uint(score_val(ms.z, ri, ci.z));
            if ((u >> 20) == b1) atomicAdd(&h[(u >> 8) & 0xFFF], 1u);
            u = __float_as_uint(score_val(ms.w, ri, ci.w));
            if ((u >> 20) == b1) atomicAdd(&h[(u >> 8) & 0xFFF], 1u);
        }
    }
    __syncthreads();
    for (int t = threadIdx.x; t < 4096; t += blockDim.x) {
        unsigned int c = h[t];
        if (c) atomicAdd(&g_hist2[t], c);
    }
}

__global__ void k_findb2() {
    __shared__ unsigned int s[256];
    const int t = threadIdx.x;
    unsigned int sum = 0;
    for (int b = t * 16; b < t * 16 + 16; b++) sum += g_hist2[b];
    s[t] = sum;
    __syncthreads();
    if (t == 0) {
        unsigned int cum = g_cntAbove1;
        int chunk = 0;
        for (int c = 255; c >= 0; c--) {
            if (cum + s[c] >= KTOP) { chunk = c; break; }
            cum += s[c];
            if (c == 0) chunk = 0;
        }
        int b;
        for (b = chunk * 16 + 15; b > chunk * 16; b--) {
            unsigned int c2 = g_hist2[b];
            if (cum + c2 >= KTOP) break;
            cum += c2;
        }
        g_thresh = (g_b1 << 20) | ((unsigned int)b << 8);
    }
}

// ------------------------- compaction ---------------------------------------
__global__ void k_compact(int N, int M) {
    const unsigned int T = g_thresh;
    const int i0 = blockIdx.x * 8;
    for (int r = 0; r < 8; r++) {
        const int i = i0 + r;
        const float ri = g_rowinv[i];
        const float4* row = (const float4*)&g_ms[(size_t)i * M];
        const float4* cin = (const float4*)g_colinv;
        const unsigned int ebase = (unsigned int)i * (unsigned int)M;
        for (int j = threadIdx.x; j < M / 4; j += blockDim.x) {
            float4 ms = row[j];
            float4 ci = cin[j];
            float v[4];
            v[0] = score_val(ms.x, ri, ci.x);
            v[1] = score_val(ms.y, ri, ci.y);
            v[2] = score_val(ms.z, ri, ci.z);
            v[3] = score_val(ms.w, ri, ci.w);
#pragma unroll
            for (int c = 0; c < 4; c++) {
                unsigned int u = __float_as_uint(v[c]);
                if (u >= T) {
                    unsigned int pos = atomicAdd(&g_candCount, 1u);
                    if (pos < CAP) {
                        unsigned int e = ebase + (unsigned int)(j * 4 + c);
                        g_cand[pos] = ((unsigned long long)u << 32)
                                    | (unsigned long long)(0xFFFFFFFFu - e);
                    }
                }
            }
        }
    }
}

// ------------------------- final rank-sort + output -------------------------
__global__ void k_final(float* __restrict__ out, int M) {
    const int C = (int)min(g_candCount, (unsigned int)CAP);
    for (int c = threadIdx.x; c < C; c += blockDim.x) {
        const unsigned long long key = g_cand[c];
        int r = 0;
        for (int o = 0; o < C; o++) r += (g_cand[o] > key);
        if (r < KTOP) {
            unsigned int u   = (unsigned int)(key >> 32);
            unsigned int idx = 0xFFFFFFFFu - (unsigned int)(key & 0xFFFFFFFFu);
            out[r]            = (float)(idx / (unsigned int)M);   // ref index
            out[KTOP + r]     = (float)(idx % (unsigned int)M);   // src index
            out[2 * KTOP + r] = __uint_as_float(u);               // score
        }
    }
}

// ------------------------- launch -------------------------------------------
extern "C" void kernel_launch(void* const* d_in, const int* in_sizes, int n_in,
                              void* d_out, int out_size) {
    const float* ref = (const float*)d_in[0];
    const float* src = (const float*)d_in[1];
    const int D = DK;
    const int N = in_sizes[0] / D;
    const int M = in_sizes[1] / D;
    float* out = (float*)d_out;

    k_zero<<<16, 256>>>();
    k_split<<<(N * D) / 256, 256>>>(ref, src);

    dim3 gg(M / 128, N / 128);
    k_gemm_mma<<<gg, 256>>>(M);

    k_rowsum<<<N, 256>>>(M);
    k_colsumA<<<dim3(M / 256, 32), 256>>>(N, M);
    k_colsumB<<<M / 256, 256>>>(M);
    k_invert<<<(N + M + 255) / 256, 256>>>(N, M);

    k_score_hist1<<<N / 8, 256>>>(N, M);
    k_findb1<<<1, 256>>>();
    k_hist2<<<N / 8, 256>>>(N, M);
    k_findb2<<<1, 256>>>();
    k_compact<<<N / 8, 256>>>(N, M);
    k_final<<<1, 1024>>>(out, M);
}

// round 8
// speedup vs baseline: 2.5571x; 1.1359x over previous
#include <cuda_runtime.h>
#include <cuda_bf16.h>
#include <math.h>
#include <stdint.h>

// Problem shape (fixed by the dataset): N = M = 4096, D = 256, K = 256.
#define NMAX 4096
#define DK   256
#define KD2  1536         // extended K: 6-term split
#define KSTEPS 48         // KD2 / 32
#define KTOP 256
#define CAP  16384
#define SAFE_BIN 2048     // skip hist2 refine when boundary-bin population <= this

// ------------------------- device scratch (no allocs allowed) ---------------
__device__ float g_ms[(size_t)NMAX * NMAX];     // exp(2*dot - 2), row-major [N, M]  (64 MB)
__device__ __nv_bfloat16 g_A2[(size_t)NMAX * KD2];
__device__ __nv_bfloat16 g_B2[(size_t)NMAX * KD2];
__device__ float g_rowp[32][NMAX];              // per-column-block row partial sums
__device__ float g_colp[32][NMAX];              // per-row-block col partial sums
__device__ float g_rowinv[NMAX];
__device__ float g_colinv[NMAX];
__device__ unsigned int g_hist1[4096];
__device__ unsigned int g_hist2[4096];
__device__ unsigned int g_b1;
__device__ unsigned int g_cntAbove1;
__device__ unsigned int g_needRefine;
__device__ unsigned int g_thresh;
__device__ unsigned int g_candCount;
__device__ unsigned long long g_cand[CAP];

// bit-exact score used identically in hist1 / hist2 / compact passes
__device__ __forceinline__ float score_val(float ms, float ri, float ci) {
    return __fmul_rn(__fmul_rn(ms, ri), __fmul_rn(ms, ci));
}

__device__ __forceinline__ uint32_t smem_u32(const void* p) {
    uint32_t a;
    asm("{ .reg .u64 t; cvta.to.shared.u64 t, %1; cvt.u32.u64 %0, t; }" : "=r"(a) : "l"(p));
    return a;
}

// ------------------------- zero mutable state (graph-replay idempotence) ----
__global__ void k_zero() {
    int t = blockIdx.x * blockDim.x + threadIdx.x;
    if (t < 4096) { g_hist1[t] = 0; g_hist2[t] = 0; }
    if (t == 0) { g_candCount = 0; g_b1 = 0; g_cntAbove1 = 0; g_thresh = 0; g_needRefine = 0; }
}

// ------------------------- fp32 -> 3-way bf16 split (6-term GEMM) -----------
// a = ah + am + al.  A2 row = [ah|ah|ah|am|am|al],  B2 row = [bh|bm|bl|bh|bm|bh]
__global__ void k_split(const float* __restrict__ A, const float* __restrict__ B) {
    int idx = blockIdx.x * blockDim.x + threadIdx.x;     // 0 .. 4096*256-1
    int row = idx >> 8;
    int c   = idx & 255;
    size_t base = (size_t)row * KD2;

    float a = A[idx];
    __nv_bfloat16 ah = __float2bfloat16(a);
    float r1 = a - __bfloat162float(ah);
    __nv_bfloat16 am = __float2bfloat16(r1);
    __nv_bfloat16 al = __float2bfloat16(r1 - __bfloat162float(am));
    g_A2[base + c]         = ah;
    g_A2[base + 256 + c]   = ah;
    g_A2[base + 512 + c]   = ah;
    g_A2[base + 768 + c]   = am;
    g_A2[base + 1024 + c]  = am;
    g_A2[base + 1280 + c]  = al;

    float b = B[idx];
    __nv_bfloat16 bh = __float2bfloat16(b);
    float s1 = b - __bfloat162float(bh);
    __nv_bfloat16 bm = __float2bfloat16(s1);
    __nv_bfloat16 bl = __float2bfloat16(s1 - __bfloat162float(bm));
    g_B2[base + c]         = bh;
    g_B2[base + 256 + c]   = bm;
    g_B2[base + 512 + c]   = bl;
    g_B2[base + 768 + c]   = bh;
    g_B2[base + 1024 + c]  = bm;
    g_B2[base + 1280 + c]  = bh;
}

// ------------------------- HMMA bf16 GEMM + exp + fused partial sums --------
// CTA = 128x128, 256 threads / 8 warps, warp tile 32x64, k-step 32, cp.async.
__global__ void __launch_bounds__(256, 2) k_gemm_mma(int M) {
    __shared__ __nv_bfloat16 As[2][128][40];
    __shared__ __nv_bfloat16 Bs[2][128][40];
    __shared__ float sm_colp[4][128];

    const int tid  = threadIdx.x;
    const int lane = tid & 31;
    const int warp = tid >> 5;        // 0..7
    const int wr   = warp >> 1;       // 0..3  (32-row band)
    const int wc   = warp & 1;        // 0..1  (64-col band)
    const int i0   = blockIdx.y * 128;
    const int j0   = blockIdx.x * 128;

    float acc[2][8][4];
#pragma unroll
    for (int a = 0; a < 2; a++)
#pragma unroll
        for (int b = 0; b < 8; b++)
#pragma unroll
            for (int c = 0; c < 4; c++) acc[a][b][c] = 0.0f;

    const __nv_bfloat16* Abase = &g_A2[(size_t)i0 * KD2];
    const __nv_bfloat16* Bbase = &g_B2[(size_t)j0 * KD2];

    const uint32_t sA = smem_u32(&As[0][0][0]);
    const uint32_t sB = smem_u32(&Bs[0][0][0]);

    const int ld_row0 = tid >> 2;
    const int ld_seg0 = tid & 3;
    const int ld_row1 = (tid + 256) >> 2;
    const int ld_seg1 = (tid + 256) & 3;

#define PREFETCH(buf, kc) do {                                                    \
    {                                                                             \
        const void* s0 = Abase + (size_t)ld_row0 * KD2 + (kc) * 32 + ld_seg0 * 8; \
        uint32_t d0 = sA + (((buf) * 128 + ld_row0) * 40 + ld_seg0 * 8) * 2;      \
        asm volatile("cp.async.cg.shared.global [%0], [%1], 16;" :: "r"(d0), "l"(s0)); \
        const void* s1 = Abase + (size_t)ld_row1 * KD2 + (kc) * 32 + ld_seg1 * 8; \
        uint32_t d1 = sA + (((buf) * 128 + ld_row1) * 40 + ld_seg1 * 8) * 2;      \
        asm volatile("cp.async.cg.shared.global [%0], [%1], 16;" :: "r"(d1), "l"(s1)); \
        const void* s2 = Bbase + (size_t)ld_row0 * KD2 + (kc) * 32 + ld_seg0 * 8; \
        uint32_t d2 = sB + (((buf) * 128 + ld_row0) * 40 + ld_seg0 * 8) * 2;      \
        asm volatile("cp.async.cg.shared.global [%0], [%1], 16;" :: "r"(d2), "l"(s2)); \
        const void* s3 = Bbase + (size_t)ld_row1 * KD2 + (kc) * 32 + ld_seg1 * 8; \
        uint32_t d3 = sB + (((buf) * 128 + ld_row1) * 40 + ld_seg1 * 8) * 2;      \
        asm volatile("cp.async.cg.shared.global [%0], [%1], 16;" :: "r"(d3), "l"(s3)); \
    }                                                                             \
    asm volatile("cp.async.commit_group;" ::: "memory");                          \
} while (0)

    const int a_row  = wr * 32 + (lane & 15);
    const int a_col  = (lane >> 4) * 8;
    const int b_row  = wc * 64 + (lane >> 4) * 8 + (lane & 7);
    const int b_col  = ((lane >> 3) & 1) * 8;

    PREFETCH(0, 0);

    for (int kc = 0; kc < KSTEPS; kc++) {
        const int cur = kc & 1;
        if (kc + 1 < KSTEPS) {
            PREFETCH(cur ^ 1, kc + 1);
            asm volatile("cp.async.wait_group 1;" ::: "memory");
        } else {
            asm volatile("cp.async.wait_group 0;" ::: "memory");
        }
        __syncthreads();

#pragma unroll
        for (int h = 0; h < 2; h++) {
            uint32_t af[2][4], bfr[4][4];
#pragma unroll
            for (int mi = 0; mi < 2; mi++) {
                uint32_t addr = sA + (((cur * 128 + a_row + mi * 16) * 40) + a_col + 16 * h) * 2;
                asm volatile("ldmatrix.sync.aligned.m8n8.x4.shared.b16 {%0,%1,%2,%3}, [%4];"
                             : "=r"(af[mi][0]), "=r"(af[mi][1]), "=r"(af[mi][2]), "=r"(af[mi][3])
                             : "r"(addr));
            }
#pragma unroll
            for (int ni = 0; ni < 4; ni++) {
                uint32_t addr = sB + (((cur * 128 + b_row + ni * 16) * 40) + b_col + 16 * h) * 2;
                asm volatile("ldmatrix.sync.aligned.m8n8.x4.shared.b16 {%0,%1,%2,%3}, [%4];"
                             : "=r"(bfr[ni][0]), "=r"(bfr[ni][1]), "=r"(bfr[ni][2]), "=r"(bfr[ni][3])
                             : "r"(addr));
            }
#pragma unroll
            for (int mi = 0; mi < 2; mi++)
#pragma unroll
                for (int nj = 0; nj < 8; nj++) {
                    const uint32_t bb0 = bfr[nj >> 1][(nj & 1) * 2];
                    const uint32_t bb1 = bfr[nj >> 1][(nj & 1) * 2 + 1];
                    asm volatile(
                        "mma.sync.aligned.m16n8k16.row.col.f32.bf16.bf16.f32 "
                        "{%0,%1,%2,%3}, {%4,%5,%6,%7}, {%8,%9}, {%0,%1,%2,%3};"
                        : "+f"(acc[mi][nj][0]), "+f"(acc[mi][nj][1]),
                          "+f"(acc[mi][nj][2]), "+f"(acc[mi][nj][3])
                        : "r"(af[mi][0]), "r"(af[mi][1]), "r"(af[mi][2]), "r"(af[mi][3]),
                          "r"(bb0), "r"(bb1));
                }
        }
        __syncthreads();
    }
#undef PREFETCH

    // epilogue: convert acc -> ms in place
#pragma unroll
    for (int mi = 0; mi < 2; mi++)
#pragma unroll
        for (int nj = 0; nj < 8; nj++)
#pragma unroll
            for (int c = 0; c < 4; c++)
                acc[mi][nj][c] = expf(fmaf(2.0f, acc[mi][nj][c], -2.0f));

    const int erow = i0 + wr * 32 + (lane >> 2);
    const int ecol = j0 + wc * 64 + (lane & 3) * 2;

    // store + fixed-order partial reductions
    float rp0 = 0.0f, rp1 = 0.0f, rp2 = 0.0f, rp3 = 0.0f;
#pragma unroll
    for (int nj = 0; nj < 8; nj++) {
        // col partials over this warp's 32 rows (lanes sharing a col differ in lane>>2)
        float c0 = acc[0][nj][0] + acc[0][nj][2] + acc[1][nj][0] + acc[1][nj][2];
        float c1 = acc[0][nj][1] + acc[0][nj][3] + acc[1][nj][1] + acc[1][nj][3];
        c0 += __shfl_xor_sync(0xFFFFFFFFu, c0, 4);
        c1 += __shfl_xor_sync(0xFFFFFFFFu, c1, 4);
        c0 += __shfl_xor_sync(0xFFFFFFFFu, c0, 8);
        c1 += __shfl_xor_sync(0xFFFFFFFFu, c1, 8);
        c0 += __shfl_xor_sync(0xFFFFFFFFu, c0, 16);
        c1 += __shfl_xor_sync(0xFFFFFFFFu, c1, 16);
        if (lane < 4) {
            sm_colp[wr][wc * 64 + nj * 8 + lane * 2]     = c0;
            sm_colp[wr][wc * 64 + nj * 8 + lane * 2 + 1] = c1;
        }
        // row partials
        rp0 += acc[0][nj][0] + acc[0][nj][1];
        rp1 += acc[0][nj][2] + acc[0][nj][3];
        rp2 += acc[1][nj][0] + acc[1][nj][1];
        rp3 += acc[1][nj][2] + acc[1][nj][3];
        // gmem stores
        float2 lo0 = make_float2(acc[0][nj][0], acc[0][nj][1]);
        float2 hi0 = make_float2(acc[0][nj][2], acc[0][nj][3]);
        float2 lo1 = make_float2(acc[1][nj][0], acc[1][nj][1]);
        float2 hi1 = make_float2(acc[1][nj][2], acc[1][nj][3]);
        *(float2*)&g_ms[(size_t)(erow)      * M + ecol + nj * 8] = lo0;
        *(float2*)&g_ms[(size_t)(erow + 8)  * M + ecol + nj * 8] = hi0;
        *(float2*)&g_ms[(size_t)(erow + 16) * M + ecol + nj * 8] = lo1;
        *(float2*)&g_ms[(size_t)(erow + 24) * M + ecol + nj * 8] = hi1;
    }
    // reduce row partials across the 4 lanes sharing each row (lane&3)
    rp0 += __shfl_xor_sync(0xFFFFFFFFu, rp0, 1);
    rp1 += __shfl_xor_sync(0xFFFFFFFFu, rp1, 1);
    rp2 += __shfl_xor_sync(0xFFFFFFFFu, rp2, 1);
    rp3 += __shfl_xor_sync(0xFFFFFFFFu, rp3, 1);
    rp0 += __shfl_xor_sync(0xFFFFFFFFu, rp0, 2);
    rp1 += __shfl_xor_sync(0xFFFFFFFFu, rp1, 2);
    rp2 += __shfl_xor_sync(0xFFFFFFFFu, rp2, 2);
    rp3 += __shfl_xor_sync(0xFFFFFFFFu, rp3, 2);
    if ((lane & 3) == 0) {
        // each warp covers half the 128-col tile; two warps (wc=0,1) per row band.
        // write to per-(jblock, wc) slots then they are summed in k_sums? No:
        // rp is over this warp's 16 cols only -> combine the two wc halves in smem.
        // Simpler: wc halves write disjoint slots g_rowp[jb*... ] -- but jb has only 32 slots.
        // Use smem to combine: reuse sm_colp? It is busy. Use shfl across warps impossible.
        // Instead: accumulate both halves via a second smem buffer.
    }
    // combine wc halves of row partials via smem (deterministic: each slot written once)
    __shared__ float sm_rowp[2][4][32];   // [wc][wr][row-in-band]
    if ((lane & 3) == 0) {
        int r = lane >> 2;                // 0..7
        sm_rowp[wc][wr][r]      = rp0;
        sm_rowp[wc][wr][r + 8]  = rp1;
        sm_rowp[wc][wr][r + 16] = rp2;
        sm_rowp[wc][wr][r + 24] = rp3;
    }
    __syncthreads();
    if (tid < 128) {
        g_rowp[blockIdx.x][i0 + tid] = sm_rowp[0][tid >> 5][tid & 31] + sm_rowp[1][tid >> 5][tid & 31];
        g_colp[blockIdx.y][j0 + tid] = sm_colp[0][tid] + sm_colp[1][tid] + sm_colp[2][tid] + sm_colp[3][tid];
    }
}

// ------------------------- reduce partials -> inverse sums ------------------
__global__ void k_sums() {
    int t = blockIdx.x * blockDim.x + threadIdx.x;    // 0..8191
    if (t < 4096) {
        float s = 0.0f;
#pragma unroll
        for (int p = 0; p < 32; p++) s += g_rowp[p][t];
        g_rowinv[t] = 1.0f / s;
    } else {
        int c = t - 4096;
        float s = 0.0f;
#pragma unroll
        for (int p = 0; p < 32; p++) s += g_colp[p][c];
        g_colinv[c] = 1.0f / s;
    }
}

// ------------------------- radix-select pass 1 ------------------------------
__device__ __forceinline__ void hist_add(unsigned int* h, unsigned int bin) {
    unsigned int mask = __match_any_sync(0xFFFFFFFFu, bin);
    unsigned int leader = __ffs(mask) - 1u;
    if ((threadIdx.x & 31) == leader) atomicAdd(&h[bin], __popc(mask));
}

__global__ void k_score_hist1(int N, int M) {
    __shared__ unsigned int h[4096];
    for (int t = threadIdx.x; t < 4096; t += blockDim.x) h[t] = 0;
    __syncthreads();
    const int i0 = blockIdx.x * 8;
    for (int r = 0; r < 8; r++) {
        const int i = i0 + r;
        const float ri = g_rowinv[i];
        const float4* row = (const float4*)&g_ms[(size_t)i * M];
        const float4* cin = (const float4*)g_colinv;
        for (int j = threadIdx.x; j < M / 4; j += blockDim.x) {
            float4 ms = row[j];
            float4 ci = cin[j];
            hist_add(h, __float_as_uint(score_val(ms.x, ri, ci.x)) >> 20);
            hist_add(h, __float_as_uint(score_val(ms.y, ri, ci.y)) >> 20);
            hist_add(h, __float_as_uint(score_val(ms.z, ri, ci.z)) >> 20);
            hist_add(h, __float_as_uint(score_val(ms.w, ri, ci.w)) >> 20);
        }
    }
    __syncthreads();
    for (int t = threadIdx.x; t < 4096; t += blockDim.x) {
        unsigned int c = h[t];
        if (c) atomicAdd(&g_hist1[t], c);
    }
}

// parallel boundary find + refine-necessity decision
__global__ void k_findb1() {
    __shared__ unsigned int s[256];
    const int t = threadIdx.x;
    unsigned int sum = 0;
    for (int b = t * 16; b < t * 16 + 16; b++) sum += g_hist1[b];
    s[t] = sum;
    __syncthreads();
    if (t == 0) {
        unsigned int cum = 0;
        int chunk = 0;
        for (int c = 255; c >= 0; c--) {
            if (cum + s[c] >= KTOP) { chunk = c; break; }
            cum += s[c];
            if (c == 0) chunk = 0;
        }
        int b;
        for (b = chunk * 16 + 15; b > chunk * 16; b--) {
            unsigned int c2 = g_hist1[b];
            if (cum + c2 >= KTOP) break;
            cum += c2;
        }
        g_b1 = (unsigned int)b;
        g_cntAbove1 = cum;
        if (cum + g_hist1[b] <= SAFE_BIN) {
            g_needRefine = 0;
            g_thresh = ((unsigned int)b) << 20;   // take whole boundary bin
        } else {
            g_needRefine = 1;
        }
    }
}

// ------------------------- radix-select pass 2 (conditional) ----------------
__global__ void k_hist2(int N, int M) {
    if (g_needRefine == 0) return;
    __shared__ unsigned int h[4096];
    for (int t = threadIdx.x; t < 4096; t += blockDim.x) h[t] = 0;
    __syncthreads();
    const unsigned int b1 = g_b1;
    const int i0 = blockIdx.x * 8;
    for (int r = 0; r < 8; r++) {
        const int i = i0 + r;
        const float ri = g_rowinv[i];
        const float4* row = (const float4*)&g_ms[(size_t)i * M];
        const float4* cin = (const float4*)g_colinv;
        for (int j = threadIdx.x; j < M / 4; j += blockDim.x) {
            float4 ms = row[j];
            float4 ci = cin[j];
            unsigned int u;
            u = __float_as_uint(score_val(ms.x, ri, ci.x));
            if ((u >> 20) == b1) atomicAdd(&h[(u >> 8) & 0xFFF], 1u);
            u = __float_as_uint(score_val(ms.y, ri, ci.y));
            if ((u >> 20) == b1) atomicAdd(&h[(u >> 8) & 0xFFF], 1u);
            u = __float_as_uint(score_val(ms.z, ri, ci.z));
            if ((u >> 20) == b1) atomicAdd(&h[(u >> 8) & 0xFFF], 1u);
            u = __float_as_uint(score_val(ms.w, ri, ci.w));
            if ((u >> 20) == b1) atomicAdd(&h[(u >> 8) & 0xFFF], 1u);
        }
    }
    __syncthreads();
    for (int t = threadIdx.x; t < 4096; t += blockDim.x) {
        unsigned int c = h[t];
        if (c) atomicAdd(&g_hist2[t], c);
    }
}

__global__ void k_findb2() {
    if (g_needRefine == 0) return;
    __shared__ unsigned int s[256];
    const int t = threadIdx.x;
    unsigned int sum = 0;
    for (int b = t * 16; b < t * 16 + 16; b++) sum += g_hist2[b];
    s[t] = sum;
    __syncthreads();
    if (t == 0) {
        unsigned int cum = g_cntAbove1;
        int chunk = 0;
        for (int c = 255; c >= 0; c--) {
            if (cum + s[c] >= KTOP) { chunk = c; break; }
            cum += s[c];
            if (c == 0) chunk = 0;
        }
        int b;
        for (b = chunk * 16 + 15; b > chunk * 16; b--) {
            unsigned int c2 = g_hist2[b];
            if (cum + c2 >= KTOP) break;
            cum += c2;
        }
        g_thresh = (g_b1 << 20) | ((unsigned int)b << 8);
    }
}

// ------------------------- compaction ---------------------------------------
__global__ void k_compact(int N, int M) {
    const unsigned int T = g_thresh;
    const int i0 = blockIdx.x * 8;
    for (int r = 0; r < 8; r++) {
        const int i = i0 + r;
        const float ri = g_rowinv[i];
        const float4* row = (const float4*)&g_ms[(size_t)i * M];
        const float4* cin = (const float4*)g_colinv;
        const unsigned int ebase = (unsigned int)i * (unsigned int)M;
        for (int j = threadIdx.x; j < M / 4; j += blockDim.x) {
            float4 ms = row[j];
            float4 ci = cin[j];
            float v[4];
            v[0] = score_val(ms.x, ri, ci.x);
            v[1] = score_val(ms.y, ri, ci.y);
            v[2] = score_val(ms.z, ri, ci.z);
            v[3] = score_val(ms.w, ri, ci.w);
#pragma unroll
            for (int c = 0; c < 4; c++) {
                unsigned int u = __float_as_uint(v[c]);
                if (u >= T) {
                    unsigned int pos = atomicAdd(&g_candCount, 1u);
                    if (pos < CAP) {
                        unsigned int e = ebase + (unsigned int)(j * 4 + c);
                        g_cand[pos] = ((unsigned long long)u << 32)
                                    | (unsigned long long)(0xFFFFFFFFu - e);
                    }
                }
            }
        }
    }
}

// ------------------------- final rank-sort + output -------------------------
__global__ void k_final(float* __restrict__ out, int M) {
    const int C = (int)min(g_candCount, (unsigned int)CAP);
    for (int c = threadIdx.x; c < C; c += blockDim.x) {
        const unsigned long long key = g_cand[c];
        int r = 0;
        for (int o = 0; o < C; o++) r += (g_cand[o] > key);
        if (r < KTOP) {
            unsigned int u   = (unsigned int)(key >> 32);
            unsigned int idx = 0xFFFFFFFFu - (unsigned int)(key & 0xFFFFFFFFu);
            out[r]            = (float)(idx / (unsigned int)M);   // ref index
            out[KTOP + r]     = (float)(idx % (unsigned int)M);   // src index
            out[2 * KTOP + r] = __uint_as_float(u);               // score
        }
    }
}

// ------------------------- launch -------------------------------------------
extern "C" void kernel_launch(void* const* d_in, const int* in_sizes, int n_in,
                              void* d_out, int out_size) {
    const float* ref = (const float*)d_in[0];
    const float* src = (const float*)d_in[1];
    const int D = DK;
    const int N = in_sizes[0] / D;
    const int M = in_sizes[1] / D;
    float* out = (float*)d_out;

    k_zero<<<16, 256>>>();
    k_split<<<(N * D) / 256, 256>>>(ref, src);

    dim3 gg(M / 128, N / 128);
    k_gemm_mma<<<gg, 256>>>(M);

    k_sums<<<32, 256>>>();

    k_score_hist1<<<N / 8, 256>>>(N, M);
    k_findb1<<<1, 256>>>();
    k_hist2<<<N / 8, 256>>>(N, M);
    k_findb2<<<1, 256>>>();
    k_compact<<<N / 8, 256>>>(N, M);
    k_final<<<1, 1024>>>(out, M);
}

// round 9
// speedup vs baseline: 3.6426x; 1.4245x over previous
#include <cuda_runtime.h>
#include <cuda_fp16.h>
#include <math.h>
#include <stdint.h>

// Problem shape (fixed by the dataset): N = M = 4096, D = 256, K = 256.
#define NMAX 4096
#define DK   256
#define KD2  768          // extended K: 3-term fp16 split [ah|ah|al] x [bh|bl|bh]
#define KSTEPS 24         // KD2 / 32
#define KTOP 256
#define CAP  16384
#define SAFE_BIN 2048     // skip hist2 refine when boundary-bin population <= this

// ------------------------- device scratch (no allocs allowed) ---------------
__device__ float g_ms[(size_t)NMAX * NMAX];     // exp(2*dot - 2), row-major [N, M]  (64 MB)
__device__ __half g_A2[(size_t)NMAX * KD2];
__device__ __half g_B2[(size_t)NMAX * KD2];
__device__ float g_rowp[32][NMAX];              // per-column-block row partial sums
__device__ float g_colp[32][NMAX];              // per-row-block col partial sums
__device__ float g_rowinv[NMAX];
__device__ float g_colinv[NMAX];
__device__ unsigned int g_hist1[4096];
__device__ unsigned int g_hist2[4096];
__device__ unsigned int g_b1;
__device__ unsigned int g_cntAbove1;
__device__ unsigned int g_needRefine;
__device__ unsigned int g_thresh;
__device__ unsigned int g_candCount;
__device__ unsigned long long g_cand[CAP];

// bit-exact score used identically in hist1 / hist2 / compact passes
__device__ __forceinline__ float score_val(float ms, float ri, float ci) {
    return __fmul_rn(__fmul_rn(ms, ri), __fmul_rn(ms, ci));
}

__device__ __forceinline__ uint32_t smem_u32(const void* p) {
    uint32_t a;
    asm("{ .reg .u64 t; cvta.to.shared.u64 t, %1; cvt.u32.u64 %0, t; }" : "=r"(a) : "l"(p));
    return a;
}

// ------------------------- zero mutable state (graph-replay idempotence) ----
__global__ void k_zero() {
    int t = blockIdx.x * blockDim.x + threadIdx.x;
    if (t < 4096) { g_hist1[t] = 0; g_hist2[t] = 0; }
    if (t == 0) { g_candCount = 0; g_b1 = 0; g_cntAbove1 = 0; g_thresh = 0; g_needRefine = 0; }
}

// ------------------------- fp32 -> fp16 hi/lo split (3-term GEMM) -----------
// a = ah + al (fp16: 11-bit mantissa each -> 22+ bits captured).
// A2 row = [ah|ah|al],  B2 row = [bh|bl|bh]
// dot(A2,B2) = ah*bh + ah*bl + al*bh ; dropped al*bl <= 2^-22 |ab| (~1.5e-8 on dot).
__global__ void k_split(const float* __restrict__ A, const float* __restrict__ B) {
    int idx = blockIdx.x * blockDim.x + threadIdx.x;     // 0 .. 4096*256-1
    int row = idx >> 8;
    int c   = idx & 255;
    size_t base = (size_t)row * KD2;

    float a = A[idx];
    __half ah = __float2half_rn(a);
    __half al = __float2half_rn(a - __half2float(ah));
    g_A2[base + c]        = ah;
    g_A2[base + 256 + c]  = ah;
    g_A2[base + 512 + c]  = al;

    float b = B[idx];
    __half bh = __float2half_rn(b);
    __half bl = __float2half_rn(b - __half2float(bh));
    g_B2[base + c]        = bh;
    g_B2[base + 256 + c]  = bl;
    g_B2[base + 512 + c]  = bh;
}

// ------------------------- HMMA fp16 GEMM + exp + fused partial sums --------
// CTA = 128x128, 256 threads / 8 warps, warp tile 32x64, k-step 32, cp.async.
__global__ void __launch_bounds__(256, 2) k_gemm_mma(int M) {
    __shared__ __half As[2][128][40];
    __shared__ __half Bs[2][128][40];
    __shared__ float sm_colp[4][128];

    const int tid  = threadIdx.x;
    const int lane = tid & 31;
    const int warp = tid >> 5;        // 0..7
    const int wr   = warp >> 1;       // 0..3  (32-row band)
    const int wc   = warp & 1;        // 0..1  (64-col band)
    const int i0   = blockIdx.y * 128;
    const int j0   = blockIdx.x * 128;

    float acc[2][8][4];
#pragma unroll
    for (int a = 0; a < 2; a++)
#pragma unroll
        for (int b = 0; b < 8; b++)
#pragma unroll
            for (int c = 0; c < 4; c++) acc[a][b][c] = 0.0f;

    const __half* Abase = &g_A2[(size_t)i0 * KD2];
    const __half* Bbase = &g_B2[(size_t)j0 * KD2];

    const uint32_t sA = smem_u32(&As[0][0][0]);
    const uint32_t sB = smem_u32(&Bs[0][0][0]);

    const int ld_row0 = tid >> 2;
    const int ld_seg0 = tid & 3;
    const int ld_row1 = (tid + 256) >> 2;
    const int ld_seg1 = (tid + 256) & 3;

#define PREFETCH(buf, kc) do {                                                    \
    {                                                                             \
        const void* s0 = Abase + (size_t)ld_row0 * KD2 + (kc) * 32 + ld_seg0 * 8; \
        uint32_t d0 = sA + (((buf) * 128 + ld_row0) * 40 + ld_seg0 * 8) * 2;      \
        asm volatile("cp.async.cg.shared.global [%0], [%1], 16;" :: "r"(d0), "l"(s0)); \
        const void* s1 = Abase + (size_t)ld_row1 * KD2 + (kc) * 32 + ld_seg1 * 8; \
        uint32_t d1 = sA + (((buf) * 128 + ld_row1) * 40 + ld_seg1 * 8) * 2;      \
        asm volatile("cp.async.cg.shared.global [%0], [%1], 16;" :: "r"(d1), "l"(s1)); \
        const void* s2 = Bbase + (size_t)ld_row0 * KD2 + (kc) * 32 + ld_seg0 * 8; \
        uint32_t d2 = sB + (((buf) * 128 + ld_row0) * 40 + ld_seg0 * 8) * 2;      \
        asm volatile("cp.async.cg.shared.global [%0], [%1], 16;" :: "r"(d2), "l"(s2)); \
        const void* s3 = Bbase + (size_t)ld_row1 * KD2 + (kc) * 32 + ld_seg1 * 8; \
        uint32_t d3 = sB + (((buf) * 128 + ld_row1) * 40 + ld_seg1 * 8) * 2;      \
        asm volatile("cp.async.cg.shared.global [%0], [%1], 16;" :: "r"(d3), "l"(s3)); \
    }                                                                             \
    asm volatile("cp.async.commit_group;" ::: "memory");                          \
} while (0)

    const int a_row  = wr * 32 + (lane & 15);
    const int a_col  = (lane >> 4) * 8;
    const int b_row  = wc * 64 + (lane >> 4) * 8 + (lane & 7);
    const int b_col  = ((lane >> 3) & 1) * 8;

    PREFETCH(0, 0);

    for (int kc = 0; kc < KSTEPS; kc++) {
        const int cur = kc & 1;
        if (kc + 1 < KSTEPS) {
            PREFETCH(cur ^ 1, kc + 1);
            asm volatile("cp.async.wait_group 1;" ::: "memory");
        } else {
            asm volatile("cp.async.wait_group 0;" ::: "memory");
        }
        __syncthreads();

#pragma unroll
        for (int h = 0; h < 2; h++) {
            uint32_t af[2][4], bfr[4][4];
#pragma unroll
            for (int mi = 0; mi < 2; mi++) {
                uint32_t addr = sA + (((cur * 128 + a_row + mi * 16) * 40) + a_col + 16 * h) * 2;
                asm volatile("ldmatrix.sync.aligned.m8n8.x4.shared.b16 {%0,%1,%2,%3}, [%4];"
                             : "=r"(af[mi][0]), "=r"(af[mi][1]), "=r"(af[mi][2]), "=r"(af[mi][3])
                             : "r"(addr));
            }
#pragma unroll
            for (int ni = 0; ni < 4; ni++) {
                uint32_t addr = sB + (((cur * 128 + b_row + ni * 16) * 40) + b_col + 16 * h) * 2;
                asm volatile("ldmatrix.sync.aligned.m8n8.x4.shared.b16 {%0,%1,%2,%3}, [%4];"
                             : "=r"(bfr[ni][0]), "=r"(bfr[ni][1]), "=r"(bfr[ni][2]), "=r"(bfr[ni][3])
                             : "r"(addr));
            }
#pragma unroll
            for (int mi = 0; mi < 2; mi++)
#pragma unroll
                for (int nj = 0; nj < 8; nj++) {
                    const uint32_t bb0 = bfr[nj >> 1][(nj & 1) * 2];
                    const uint32_t bb1 = bfr[nj >> 1][(nj & 1) * 2 + 1];
                    asm volatile(
                        "mma.sync.aligned.m16n8k16.row.col.f32.f16.f16.f32 "
                        "{%0,%1,%2,%3}, {%4,%5,%6,%7}, {%8,%9}, {%0,%1,%2,%3};"
                        : "+f"(acc[mi][nj][0]), "+f"(acc[mi][nj][1]),
                          "+f"(acc[mi][nj][2]), "+f"(acc[mi][nj][3])
                        : "r"(af[mi][0]), "r"(af[mi][1]), "r"(af[mi][2]), "r"(af[mi][3]),
                          "r"(bb0), "r"(bb1));
                }
        }
        __syncthreads();
    }
#undef PREFETCH

    // epilogue: convert acc -> ms in place
#pragma unroll
    for (int mi = 0; mi < 2; mi++)
#pragma unroll
        for (int nj = 0; nj < 8; nj++)
#pragma unroll
            for (int c = 0; c < 4; c++)
                acc[mi][nj][c] = expf(fmaf(2.0f, acc[mi][nj][c], -2.0f));

    const int erow = i0 + wr * 32 + (lane >> 2);
    const int ecol = j0 + wc * 64 + (lane & 3) * 2;

    // store + fixed-order partial reductions
    float rp0 = 0.0f, rp1 = 0.0f, rp2 = 0.0f, rp3 = 0.0f;
#pragma unroll
    for (int nj = 0; nj < 8; nj++) {
        float c0 = acc[0][nj][0] + acc[0][nj][2] + acc[1][nj][0] + acc[1][nj][2];
        float c1 = acc[0][nj][1] + acc[0][nj][3] + acc[1][nj][1] + acc[1][nj][3];
        c0 += __shfl_xor_sync(0xFFFFFFFFu, c0, 4);
        c1 += __shfl_xor_sync(0xFFFFFFFFu, c1, 4);
        c0 += __shfl_xor_sync(0xFFFFFFFFu, c0, 8);
        c1 += __shfl_xor_sync(0xFFFFFFFFu, c1, 8);
        c0 += __shfl_xor_sync(0xFFFFFFFFu, c0, 16);
        c1 += __shfl_xor_sync(0xFFFFFFFFu, c1, 16);
        if (lane < 4) {
            sm_colp[wr][wc * 64 + nj * 8 + lane * 2]     = c0;
            sm_colp[wr][wc * 64 + nj * 8 + lane * 2 + 1] = c1;
        }
        rp0 += acc[0][nj][0] + acc[0][nj][1];
        rp1 += acc[0][nj][2] + acc[0][nj][3];
        rp2 += acc[1][nj][0] + acc[1][nj][1];
        rp3 += acc[1][nj][2] + acc[1][nj][3];
        float2 lo0 = make_float2(acc[0][nj][0], acc[0][nj][1]);
        float2 hi0 = make_float2(acc[0][nj][2], acc[0][nj][3]);
        float2 lo1 = make_float2(acc[1][nj][0], acc[1][nj][1]);
        float2 hi1 = make_float2(acc[1][nj][2], acc[1][nj][3]);
        *(float2*)&g_ms[(size_t)(erow)      * M + ecol + nj * 8] = lo0;
        *(float2*)&g_ms[(size_t)(erow + 8)  * M + ecol + nj * 8] = hi0;
        *(float2*)&g_ms[(size_t)(erow + 16) * M + ecol + nj * 8] = lo1;
        *(float2*)&g_ms[(size_t)(erow + 24) * M + ecol + nj * 8] = hi1;
    }
    rp0 += __shfl_xor_sync(0xFFFFFFFFu, rp0, 1);
    rp1 += __shfl_xor_sync(0xFFFFFFFFu, rp1, 1);
    rp2 += __shfl_xor_sync(0xFFFFFFFFu, rp2, 1);
    rp3 += __shfl_xor_sync(0xFFFFFFFFu, rp3, 1);
    rp0 += __shfl_xor_sync(0xFFFFFFFFu, rp0, 2);
    rp1 += __shfl_xor_sync(0xFFFFFFFFu, rp1, 2);
    rp2 += __shfl_xor_sync(0xFFFFFFFFu, rp2, 2);
    rp3 += __shfl_xor_sync(0xFFFFFFFFu, rp3, 2);
    __shared__ float sm_rowp[2][4][32];   // [wc][wr][row-in-band]
    if ((lane & 3) == 0) {
        int r = lane >> 2;                // 0..7
        sm_rowp[wc][wr][r]      = rp0;
        sm_rowp[wc][wr][r + 8]  = rp1;
        sm_rowp[wc][wr][r + 16] = rp2;
        sm_rowp[wc][wr][r + 24] = rp3;
    }
    __syncthreads();
    if (tid < 128) {
        g_rowp[blockIdx.x][i0 + tid] = sm_rowp[0][tid >> 5][tid & 31] + sm_rowp[1][tid >> 5][tid & 31];
        g_colp[blockIdx.y][j0 + tid] = sm_colp[0][tid] + sm_colp[1][tid] + sm_colp[2][tid] + sm_colp[3][tid];
    }
}

// ------------------------- reduce partials -> inverse sums ------------------
__global__ void k_sums() {
    int t = blockIdx.x * blockDim.x + threadIdx.x;    // 0..8191
    if (t < 4096) {
        float s = 0.0f;
#pragma unroll
        for (int p = 0; p < 32; p++) s += g_rowp[p][t];
        g_rowinv[t] = 1.0f / s;
    } else {
        int c = t - 4096;
        float s = 0.0f;
#pragma unroll
        for (int p = 0; p < 32; p++) s += g_colp[p][c];
        g_colinv[c] = 1.0f / s;
    }
}

// ------------------------- radix-select pass 1 ------------------------------
__device__ __forceinline__ void hist_add(unsigned int* h, unsigned int bin) {
    unsigned int mask = __match_any_sync(0xFFFFFFFFu, bin);
    unsigned int leader = __ffs(mask) - 1u;
    if ((threadIdx.x & 31) == leader) atomicAdd(&h[bin], __popc(mask));
}

__global__ void k_score_hist1(int N, int M) {
    __shared__ unsigned int h[4096];
    for (int t = threadIdx.x; t < 4096; t += blockDim.x) h[t] = 0;
    __syncthreads();
    const int i0 = blockIdx.x * 8;
    for (int r = 0; r < 8; r++) {
        const int i = i0 + r;
        const float ri = g_rowinv[i];
        const float4* row = (const float4*)&g_ms[(size_t)i * M];
        const float4* cin = (const float4*)g_colinv;
        for (int j = threadIdx.x; j < M / 4; j += blockDim.x) {
            float4 ms = row[j];
            float4 ci = cin[j];
            hist_add(h, __float_as_uint(score_val(ms.x, ri, ci.x)) >> 20);
            hist_add(h, __float_as_uint(score_val(ms.y, ri, ci.y)) >> 20);
            hist_add(h, __float_as_uint(score_val(ms.z, ri, ci.z)) >> 20);
            hist_add(h, __float_as_uint(score_val(ms.w, ri, ci.w)) >> 20);
        }
    }
    __syncthreads();
    for (int t = threadIdx.x; t < 4096; t += blockDim.x) {
        unsigned int c = h[t];
        if (c) atomicAdd(&g_hist1[t], c);
    }
}

// parallel boundary find + refine-necessity decision
__global__ void k_findb1() {
    __shared__ unsigned int s[256];
    const int t = threadIdx.x;
    unsigned int sum = 0;
    for (int b = t * 16; b < t * 16 + 16; b++) sum += g_hist1[b];
    s[t] = sum;
    __syncthreads();
    if (t == 0) {
        unsigned int cum = 0;
        int chunk = 0;
        for (int c = 255; c >= 0; c--) {
            if (cum + s[c] >= KTOP) { chunk = c; break; }
            cum += s[c];
            if (c == 0) chunk = 0;
        }
        int b;
        for (b = chunk * 16 + 15; b > chunk * 16; b--) {
            unsigned int c2 = g_hist1[b];
            if (cum + c2 >= KTOP) break;
            cum += c2;
        }
        g_b1 = (unsigned int)b;
        g_cntAbove1 = cum;
        if (cum + g_hist1[b] <= SAFE_BIN) {
            g_needRefine = 0;
            g_thresh = ((unsigned int)b) << 20;   // take whole boundary bin
        } else {
            g_needRefine = 1;
        }
    }
}

// ------------------------- radix-select pass 2 (conditional) ----------------
__global__ void k_hist2(int N, int M) {
    if (g_needRefine == 0) return;
    __shared__ unsigned int h[4096];
    for (int t = threadIdx.x; t < 4096; t += blockDim.x) h[t] = 0;
    __syncthreads();
    const unsigned int b1 = g_b1;
    const int i0 = blockIdx.x * 8;
    for (int r = 0; r < 8; r++) {
        const int i = i0 + r;
        const float ri = g_rowinv[i];
        const float4* row = (const float4*)&g_ms[(size_t)i * M];
        const float4* cin = (const float4*)g_colinv;
        for (int j = threadIdx.x; j < M / 4; j += blockDim.x) {
            float4 ms = row[j];
            float4 ci = cin[j];
            unsigned int u;
            u = __float_as_uint(score_val(ms.x, ri, ci.x));
            if ((u >> 20) == b1) atomicAdd(&h[(u >> 8) & 0xFFF], 1u);
            u = __float_as_uint(score_val(ms.y, ri, ci.y));
            if ((u >> 20) == b1) atomicAdd(&h[(u >> 8) & 0xFFF], 1u);
            u = __float_as_uint(score_val(ms.z, ri, ci.z));
            if ((u >> 20) == b1) atomicAdd(&h[(u >> 8) & 0xFFF], 1u);
            u = __float_as_uint(score_val(ms.w, ri, ci.w));
            if ((u >> 20) == b1) atomicAdd(&h[(u >> 8) & 0xFFF], 1u);
        }
    }
    __syncthreads();
    for (int t = threadIdx.x; t < 4096; t += blockDim.x) {
        unsigned int c = h[t];
        if (c) atomicAdd(&g_hist2[t], c);
    }
}

__global__ void k_findb2() {
    if (g_needRefine == 0) return;
    __shared__ unsigned int s[256];
    const int t = threadIdx.x;
    unsigned int sum = 0;
    for (int b = t * 16; b < t * 16 + 16; b++) sum += g_hist2[b];
    s[t] = sum;
    __syncthreads();
    if (t == 0) {
        unsigned int cum = g_cntAbove1;
        int chunk = 0;
        for (int c = 255; c >= 0; c--) {
            if (cum + s[c] >= KTOP) { chunk = c; break; }
            cum += s[c];
            if (c == 0) chunk = 0;
        }
        int b;
        for (b = chunk * 16 + 15; b > chunk * 16; b--) {
            unsigned int c2 = g_hist2[b];
            if (cum + c2 >= KTOP) break;
            cum += c2;
        }
        g_thresh = (g_b1 << 20) | ((unsigned int)b << 8);
    }
}

// ------------------------- compaction ---------------------------------------
__global__ void k_compact(int N, int M) {
    const unsigned int T = g_thresh;
    const int i0 = blockIdx.x * 8;
    for (int r = 0; r < 8; r++) {
        const int i = i0 + r;
        const float ri = g_rowinv[i];
        const float4* row = (const float4*)&g_ms[(size_t)i * M];
        const float4* cin = (const float4*)g_colinv;
        const unsigned int ebase = (unsigned int)i * (unsigned int)M;
        for (int j = threadIdx.x; j < M / 4; j += blockDim.x) {
            float4 ms = row[j];
            float4 ci = cin[j];
            float v[4];
            v[0] = score_val(ms.x, ri, ci.x);
            v[1] = score_val(ms.y, ri, ci.y);
            v[2] = score_val(ms.z, ri, ci.z);
            v[3] = score_val(ms.w, ri, ci.w);
#pragma unroll
            for (int c = 0; c < 4; c++) {
                unsigned int u = __float_as_uint(v[c]);
                if (u >= T) {
                    unsigned int pos = atomicAdd(&g_candCount, 1u);
                    if (pos < CAP) {
                        unsigned int e = ebase + (unsigned int)(j * 4 + c);
                        g_cand[pos] = ((unsigned long long)u << 32)
                                    | (unsigned long long)(0xFFFFFFFFu - e);
                    }
                }
            }
        }
    }
}

// ------------------------- final rank-sort + output -------------------------
__global__ void k_final(float* __restrict__ out, int M) {
    const int C = (int)min(g_candCount, (unsigned int)CAP);
    for (int c = threadIdx.x; c < C; c += blockDim.x) {
        const unsigned long long key = g_cand[c];
        int r = 0;
        for (int o = 0; o < C; o++) r += (g_cand[o] > key);
        if (r < KTOP) {
            unsigned int u   = (unsigned int)(key >> 32);
            unsigned int idx = 0xFFFFFFFFu - (unsigned int)(key & 0xFFFFFFFFu);
            out[r]            = (float)(idx / (unsigned int)M);   // ref index
            out[KTOP + r]     = (float)(idx % (unsigned int)M);   // src index
            out[2 * KTOP + r] = __uint_as_float(u);               // score
        }
    }
}

// ------------------------- launch -------------------------------------------
extern "C" void kernel_launch(void* const* d_in, const int* in_sizes, int n_in,
                              void* d_out, int out_size) {
    const float* ref = (const float*)d_in[0];
    const float* src = (const float*)d_in[1];
    const int D = DK;
    const int N = in_sizes[0] / D;
    const int M = in_sizes[1] / D;
    float* out = (float*)d_out;

    k_zero<<<16, 256>>>();
    k_split<<<(N * D) / 256, 256>>>(ref, src);

    dim3 gg(M / 128, N / 128);
    k_gemm_mma<<<gg, 256>>>(M);

    k_sums<<<32, 256>>>();

    k_score_hist1<<<N / 8, 256>>>(N, M);
    k_findb1<<<1, 256>>>();
    k_hist2<<<N / 8, 256>>>(N, M);
    k_findb2<<<1, 256>>>();
    k_compact<<<N / 8, 256>>>(N, M);
    k_final<<<1, 1024>>>(out, M);
}

// round 10
// speedup vs baseline: 5.1143x; 1.4040x over previous
#include <cuda_runtime.h>
#include <cuda_fp16.h>
#include <math.h>
#include <stdint.h>

// Problem shape (fixed by the dataset): N = M = 4096, D = 256, K = 256.
#define NMAX 4096
#define DK   256
#define KD2  768          // extended K: 3-term fp16 split [ah|ah|al] x [bh|bl|bh]
#define KSTEPS 12         // KD2 / 64
#define KTOP 256
#define CAP  16384
#define SAFE_BIN 2048     // skip hist2 refine when boundary-bin population <= this

#define SROW 72           // smem row stride in halves (64 + 8 pad, conflict-free)
#define ABUF_HALVES (2 * 128 * SROW)
#define DYN_SMEM (2 * ABUF_HALVES * 2)   // A + B double-buffered, bytes = 73728

// ------------------------- device scratch (no allocs allowed) ---------------
__device__ float g_ms[(size_t)NMAX * NMAX];     // exp(2*dot - 2), row-major [N, M]  (64 MB)
__device__ __half g_A2[(size_t)NMAX * KD2];
__device__ __half g_B2[(size_t)NMAX * KD2];
__device__ float g_rowp[32][NMAX];              // per-column-block row partial sums
__device__ float g_colp[32][NMAX];              // per-row-block col partial sums
__device__ float g_rowinv[NMAX];
__device__ float g_colinv[NMAX];
__device__ unsigned int g_hist1[4096];
__device__ unsigned int g_hist2[4096];
__device__ unsigned int g_b1;
__device__ unsigned int g_cntAbove1;
__device__ unsigned int g_needRefine;
__device__ unsigned int g_thresh;
__device__ unsigned int g_candCount;
__device__ unsigned long long g_cand[CAP];

// bit-exact score used identically in hist1 / hist2 / compact passes
__device__ __forceinline__ float score_val(float ms, float ri, float ci) {
    return __fmul_rn(__fmul_rn(ms, ri), __fmul_rn(ms, ci));
}

__device__ __forceinline__ uint32_t smem_u32(const void* p) {
    uint32_t a;
    asm("{ .reg .u64 t; cvta.to.shared.u64 t, %1; cvt.u32.u64 %0, t; }" : "=r"(a) : "l"(p));
    return a;
}

// ------------------------- zero mutable state (graph-replay idempotence) ----
__global__ void k_zero() {
    int t = blockIdx.x * blockDim.x + threadIdx.x;
    if (t < 4096) { g_hist1[t] = 0; g_hist2[t] = 0; }
    if (t == 0) { g_candCount = 0; g_b1 = 0; g_cntAbove1 = 0; g_thresh = 0; g_needRefine = 0; }
}

// ------------------------- fp32 -> fp16 hi/lo split (3-term GEMM) -----------
// a = ah + al.  A2 row = [ah|ah|al],  B2 row = [bh|bl|bh]
// dot(A2,B2) = ah*bh + ah*bl + al*bh ; dropped al*bl <= 2^-22 |ab|.
__global__ void k_split(const float* __restrict__ A, const float* __restrict__ B) {
    int idx = blockIdx.x * blockDim.x + threadIdx.x;     // 0 .. 4096*256-1
    int row = idx >> 8;
    int c   = idx & 255;
    size_t base = (size_t)row * KD2;

    float a = A[idx];
    __half ah = __float2half_rn(a);
    __half al = __float2half_rn(a - __half2float(ah));
    g_A2[base + c]        = ah;
    g_A2[base + 256 + c]  = ah;
    g_A2[base + 512 + c]  = al;

    float b = B[idx];
    __half bh = __float2half_rn(b);
    __half bl = __float2half_rn(b - __half2float(bh));
    g_B2[base + c]        = bh;
    g_B2[base + 256 + c]  = bl;
    g_B2[base + 512 + c]  = bh;
}

// ------------------------- HMMA fp16 GEMM + exp + fused partial sums --------
// CTA = 128x128, 256 threads / 8 warps, warp tile 32x64, k-step 64, cp.async.
__global__ void __launch_bounds__(256, 2) k_gemm_mma(int M) {
    extern __shared__ __half dyn[];
    __half* Asm = dyn;                    // [2][128][SROW]
    __half* Bsm = dyn + ABUF_HALVES;      // [2][128][SROW]
    __shared__ float sm_colp[4][128];
    __shared__ float sm_rowp[2][4][32];

    const int tid  = threadIdx.x;
    const int lane = tid & 31;
    const int warp = tid >> 5;        // 0..7
    const int wr   = warp >> 1;       // 0..3  (32-row band)
    const int wc   = warp & 1;        // 0..1  (64-col band)
    const int i0   = blockIdx.y * 128;
    const int j0   = blockIdx.x * 128;

    float acc[2][8][4];
#pragma unroll
    for (int a = 0; a < 2; a++)
#pragma unroll
        for (int b = 0; b < 8; b++)
#pragma unroll
            for (int c = 0; c < 4; c++) acc[a][b][c] = 0.0f;

    const __half* Abase = &g_A2[(size_t)i0 * KD2];
    const __half* Bbase = &g_B2[(size_t)j0 * KD2];

    const uint32_t sA = smem_u32(Asm);
    const uint32_t sB = smem_u32(Bsm);

// 1024 16B-chunks per (matrix, buffer); 256 threads -> 4 chunks each.
#define PREFETCH(buf, kc) do {                                                        \
    _Pragma("unroll")                                                                 \
    for (int i = 0; i < 4; i++) {                                                     \
        int idx = tid + 256 * i;                                                      \
        int row = idx >> 3;                                                           \
        int seg = idx & 7;                                                            \
        const void* sa = Abase + (size_t)row * KD2 + (kc) * 64 + seg * 8;             \
        uint32_t da = sA + (((buf) * 128 + row) * SROW + seg * 8) * 2;                \
        asm volatile("cp.async.cg.shared.global [%0], [%1], 16;" :: "r"(da), "l"(sa));\
        const void* sb = Bbase + (size_t)row * KD2 + (kc) * 64 + seg * 8;             \
        uint32_t db = sB + (((buf) * 128 + row) * SROW + seg * 8) * 2;                \
        asm volatile("cp.async.cg.shared.global [%0], [%1], 16;" :: "r"(db), "l"(sb));\
    }                                                                                 \
    asm volatile("cp.async.commit_group;" ::: "memory");                              \
} while (0)

    const int a_row  = wr * 32 + (lane & 15);
    const int a_col  = (lane >> 4) * 8;
    const int b_row  = wc * 64 + (lane >> 4) * 8 + (lane & 7);
    const int b_col  = ((lane >> 3) & 1) * 8;

    PREFETCH(0, 0);

    for (int kc = 0; kc < KSTEPS; kc++) {
        const int cur = kc & 1;
        if (kc + 1 < KSTEPS) {
            PREFETCH(cur ^ 1, kc + 1);
            asm volatile("cp.async.wait_group 1;" ::: "memory");
        } else {
            asm volatile("cp.async.wait_group 0;" ::: "memory");
        }
        __syncthreads();

#pragma unroll
        for (int h = 0; h < 4; h++) {
            uint32_t af[2][4], bfr[4][4];
#pragma unroll
            for (int mi = 0; mi < 2; mi++) {
                uint32_t addr = sA + (((cur * 128 + a_row + mi * 16) * SROW) + a_col + 16 * h) * 2;
                asm volatile("ldmatrix.sync.aligned.m8n8.x4.shared.b16 {%0,%1,%2,%3}, [%4];"
                             : "=r"(af[mi][0]), "=r"(af[mi][1]), "=r"(af[mi][2]), "=r"(af[mi][3])
                             : "r"(addr));
            }
#pragma unroll
            for (int ni = 0; ni < 4; ni++) {
                uint32_t addr = sB + (((cur * 128 + b_row + ni * 16) * SROW) + b_col + 16 * h) * 2;
                asm volatile("ldmatrix.sync.aligned.m8n8.x4.shared.b16 {%0,%1,%2,%3}, [%4];"
                             : "=r"(bfr[ni][0]), "=r"(bfr[ni][1]), "=r"(bfr[ni][2]), "=r"(bfr[ni][3])
                             : "r"(addr));
            }
#pragma unroll
            for (int mi = 0; mi < 2; mi++)
#pragma unroll
                for (int nj = 0; nj < 8; nj++) {
                    const uint32_t bb0 = bfr[nj >> 1][(nj & 1) * 2];
                    const uint32_t bb1 = bfr[nj >> 1][(nj & 1) * 2 + 1];
                    asm volatile(
                        "mma.sync.aligned.m16n8k16.row.col.f32.f16.f16.f32 "
                        "{%0,%1,%2,%3}, {%4,%5,%6,%7}, {%8,%9}, {%0,%1,%2,%3};"
                        : "+f"(acc[mi][nj][0]), "+f"(acc[mi][nj][1]),
                          "+f"(acc[mi][nj][2]), "+f"(acc[mi][nj][3])
                        : "r"(af[mi][0]), "r"(af[mi][1]), "r"(af[mi][2]), "r"(af[mi][3]),
                          "r"(bb0), "r"(bb1));
                }
        }
        __syncthreads();
    }
#undef PREFETCH

    // epilogue: convert acc -> ms in place
#pragma unroll
    for (int mi = 0; mi < 2; mi++)
#pragma unroll
        for (int nj = 0; nj < 8; nj++)
#pragma unroll
            for (int c = 0; c < 4; c++)
                acc[mi][nj][c] = expf(fmaf(2.0f, acc[mi][nj][c], -2.0f));

    const int erow = i0 + wr * 32 + (lane >> 2);
    const int ecol = j0 + wc * 64 + (lane & 3) * 2;

    float rp0 = 0.0f, rp1 = 0.0f, rp2 = 0.0f, rp3 = 0.0f;
#pragma unroll
    for (int nj = 0; nj < 8; nj++) {
        float c0 = acc[0][nj][0] + acc[0][nj][2] + acc[1][nj][0] + acc[1][nj][2];
        float c1 = acc[0][nj][1] + acc[0][nj][3] + acc[1][nj][1] + acc[1][nj][3];
        c0 += __shfl_xor_sync(0xFFFFFFFFu, c0, 4);
        c1 += __shfl_xor_sync(0xFFFFFFFFu, c1, 4);
        c0 += __shfl_xor_sync(0xFFFFFFFFu, c0, 8);
        c1 += __shfl_xor_sync(0xFFFFFFFFu, c1, 8);
        c0 += __shfl_xor_sync(0xFFFFFFFFu, c0, 16);
        c1 += __shfl_xor_sync(0xFFFFFFFFu, c1, 16);
        if (lane < 4) {
            sm_colp[wr][wc * 64 + nj * 8 + lane * 2]     = c0;
            sm_colp[wr][wc * 64 + nj * 8 + lane * 2 + 1] = c1;
        }
        rp0 += acc[0][nj][0] + acc[0][nj][1];
        rp1 += acc[0][nj][2] + acc[0][nj][3];
        rp2 += acc[1][nj][0] + acc[1][nj][1];
        rp3 += acc[1][nj][2] + acc[1][nj][3];
        float2 lo0 = make_float2(acc[0][nj][0], acc[0][nj][1]);
        float2 hi0 = make_float2(acc[0][nj][2], acc[0][nj][3]);
        float2 lo1 = make_float2(acc[1][nj][0], acc[1][nj][1]);
        float2 hi1 = make_float2(acc[1][nj][2], acc[1][nj][3]);
        *(float2*)&g_ms[(size_t)(erow)      * M + ecol + nj * 8] = lo0;
        *(float2*)&g_ms[(size_t)(erow + 8)  * M + ecol + nj * 8] = hi0;
        *(float2*)&g_ms[(size_t)(erow + 16) * M + ecol + nj * 8] = lo1;
        *(float2*)&g_ms[(size_t)(erow + 24) * M + ecol + nj * 8] = hi1;
    }
    rp0 += __shfl_xor_sync(0xFFFFFFFFu, rp0, 1);
    rp1 += __shfl_xor_sync(0xFFFFFFFFu, rp1, 1);
    rp2 += __shfl_xor_sync(0xFFFFFFFFu, rp2, 1);
    rp3 += __shfl_xor_sync(0xFFFFFFFFu, rp3, 1);
    rp0 += __shfl_xor_sync(0xFFFFFFFFu, rp0, 2);
    rp1 += __shfl_xor_sync(0xFFFFFFFFu, rp1, 2);
    rp2 += __shfl_xor_sync(0xFFFFFFFFu, rp2, 2);
    rp3 += __shfl_xor_sync(0xFFFFFFFFu, rp3, 2);
    if ((lane & 3) == 0) {
        int r = lane >> 2;                // 0..7
        sm_rowp[wc][wr][r]      = rp0;
        sm_rowp[wc][wr][r + 8]  = rp1;
        sm_rowp[wc][wr][r + 16] = rp2;
        sm_rowp[wc][wr][r + 24] = rp3;
    }
    __syncthreads();
    if (tid < 128) {
        g_rowp[blockIdx.x][i0 + tid] = sm_rowp[0][tid >> 5][tid & 31] + sm_rowp[1][tid >> 5][tid & 31];
        g_colp[blockIdx.y][j0 + tid] = sm_colp[0][tid] + sm_colp[1][tid] + sm_colp[2][tid] + sm_colp[3][tid];
    }
}

// ------------------------- reduce partials -> inverse sums ------------------
__global__ void k_sums() {
    int t = blockIdx.x * blockDim.x + threadIdx.x;    // 0..8191
    if (t < 4096) {
        float s = 0.0f;
#pragma unroll
        for (int p = 0; p < 32; p++) s += g_rowp[p][t];
        g_rowinv[t] = 1.0f / s;
    } else {
        int c = t - 4096;
        float s = 0.0f;
#pragma unroll
        for (int p = 0; p < 32; p++) s += g_colp[p][c];
        g_colinv[c] = 1.0f / s;
    }
}

// ------------------------- radix-select pass 1 ------------------------------
__global__ void k_score_hist1(int N, int M) {
    __shared__ unsigned int h[4096];
    for (int t = threadIdx.x; t < 4096; t += blockDim.x) h[t] = 0;
    __syncthreads();
    const int i0 = blockIdx.x * 4;
    for (int r = 0; r < 4; r++) {
        const int i = i0 + r;
        const float ri = g_rowinv[i];
        const float4* row = (const float4*)&g_ms[(size_t)i * M];
        const float4* cin = (const float4*)g_colinv;
        for (int j = threadIdx.x; j < M / 4; j += blockDim.x) {
            float4 ms = row[j];
            float4 ci = cin[j];
            atomicAdd(&h[__float_as_uint(score_val(ms.x, ri, ci.x)) >> 20], 1u);
            atomicAdd(&h[__float_as_uint(score_val(ms.y, ri, ci.y)) >> 20], 1u);
            atomicAdd(&h[__float_as_uint(score_val(ms.z, ri, ci.z)) >> 20], 1u);
            atomicAdd(&h[__float_as_uint(score_val(ms.w, ri, ci.w)) >> 20], 1u);
        }
    }
    __syncthreads();
    for (int t = threadIdx.x; t < 4096; t += blockDim.x) {
        unsigned int c = h[t];
        if (c) atomicAdd(&g_hist1[t], c);
    }
}

// parallel boundary find + refine-necessity decision
__global__ void k_findb1() {
    __shared__ unsigned int s[256];
    const int t = threadIdx.x;
    unsigned int sum = 0;
    for (int b = t * 16; b < t * 16 + 16; b++) sum += g_hist1[b];
    s[t] = sum;
    __syncthreads();
    if (t == 0) {
        unsigned int cum = 0;
        int chunk = 0;
        for (int c = 255; c >= 0; c--) {
            if (cum + s[c] >= KTOP) { chunk = c; break; }
            cum += s[c];
            if (c == 0) chunk = 0;
        }
        int b;
        for (b = chunk * 16 + 15; b > chunk * 16; b--) {
            unsigned int c2 = g_hist1[b];
            if (cum + c2 >= KTOP) break;
            cum += c2;
        }
        g_b1 = (unsigned int)b;
        g_cntAbove1 = cum;
        if (cum + g_hist1[b] <= SAFE_BIN) {
            g_needRefine = 0;
            g_thresh = ((unsigned int)b) << 20;   // take whole boundary bin
        } else {
            g_needRefine = 1;
        }
    }
}

// ------------------------- radix-select pass 2 (conditional) ----------------
__global__ void k_hist2(int N, int M) {
    if (g_needRefine == 0) return;
    __shared__ unsigned int h[4096];
    for (int t = threadIdx.x; t < 4096; t += blockDim.x) h[t] = 0;
    __syncthreads();
    const unsigned int b1 = g_b1;
    const int i0 = blockIdx.x * 4;
    for (int r = 0; r < 4; r++) {
        const int i = i0 + r;
        const float ri = g_rowinv[i];
        const float4* row = (const float4*)&g_ms[(size_t)i * M];
        const float4* cin = (const float4*)g_colinv;
        for (int j = threadIdx.x; j < M / 4; j += blockDim.x) {
            float4 ms = row[j];
            float4 ci = cin[j];
            unsigned int u;
            u = __float_as_uint(score_val(ms.x, ri, ci.x));
            if ((u >> 20) == b1) atomicAdd(&h[(u >> 8) & 0xFFF], 1u);
            u = __float_as_uint(score_val(ms.y, ri, ci.y));
            if ((u >> 20) == b1) atomicAdd(&h[(u >> 8) & 0xFFF], 1u);
            u = __float_as_uint(score_val(ms.z, ri, ci.z));
            if ((u >> 20) == b1) atomicAdd(&h[(u >> 8) & 0xFFF], 1u);
            u = __float_as_uint(score_val(ms.w, ri, ci.w));
            if ((u >> 20) == b1) atomicAdd(&h[(u >> 8) & 0xFFF], 1u);
        }
    }
    __syncthreads();
    for (int t = threadIdx.x; t < 4096; t += blockDim.x) {
        unsigned int c = h[t];
        if (c) atomicAdd(&g_hist2[t], c);
    }
}

__global__ void k_findb2() {
    if (g_needRefine == 0) return;
    __shared__ unsigned int s[256];
    const int t = threadIdx.x;
    unsigned int sum = 0;
    for (int b = t * 16; b < t * 16 + 16; b++) sum += g_hist2[b];
    s[t] = sum;
    __syncthreads();
    if (t == 0) {
        unsigned int cum = g_cntAbove1;
        int chunk = 0;
        for (int c = 255; c >= 0; c--) {
            if (cum + s[c] >= KTOP) { chunk = c; break; }
            cum += s[c];
            if (c == 0) chunk = 0;
        }
        int b;
        for (b = chunk * 16 + 15; b > chunk * 16; b--) {
            unsigned int c2 = g_hist2[b];
            if (cum + c2 >= KTOP) break;
            cum += c2;
        }
        g_thresh = (g_b1 << 20) | ((unsigned int)b << 8);
    }
}

// ------------------------- compaction ---------------------------------------
__global__ void k_compact(int N, int M) {
    const unsigned int T = g_thresh;
    const int i0 = blockIdx.x * 4;
    for (int r = 0; r < 4; r++) {
        const int i = i0 + r;
        const float ri = g_rowinv[i];
        const float4* row = (const float4*)&g_ms[(size_t)i * M];
        const float4* cin = (const float4*)g_colinv;
        const unsigned int ebase = (unsigned int)i * (unsigned int)M;
        for (int j = threadIdx.x; j < M / 4; j += blockDim.x) {
            float4 ms = row[j];
            float4 ci = cin[j];
            float v[4];
            v[0] = score_val(ms.x, ri, ci.x);
            v[1] = score_val(ms.y, ri, ci.y);
            v[2] = score_val(ms.z, ri, ci.z);
            v[3] = score_val(ms.w, ri, ci.w);
#pragma unroll
            for (int c = 0; c < 4; c++) {
                unsigned int u = __float_as_uint(v[c]);
                if (u >= T) {
                    unsigned int pos = atomicAdd(&g_candCount, 1u);
                    if (pos < CAP) {
                        unsigned int e = ebase + (unsigned int)(j * 4 + c);
                        g_cand[pos] = ((unsigned long long)u << 32)
                                    | (unsigned long long)(0xFFFFFFFFu - e);
                    }
                }
            }
        }
    }
}

// ------------------------- final rank-sort + output -------------------------
__global__ void k_final(float* __restrict__ out, int M) {
    const int C = (int)min(g_candCount, (unsigned int)CAP);
    for (int c = threadIdx.x; c < C; c += blockDim.x) {
        const unsigned long long key = g_cand[c];
        int r = 0;
        for (int o = 0; o < C; o++) r += (g_cand[o] > key);
        if (r < KTOP) {
            unsigned int u   = (unsigned int)(key >> 32);
            unsigned int idx = 0xFFFFFFFFu - (unsigned int)(key & 0xFFFFFFFFu);
            out[r]            = (float)(idx / (unsigned int)M);   // ref index
            out[KTOP + r]     = (float)(idx % (unsigned int)M);   // src index
            out[2 * KTOP + r] = __uint_as_float(u);               // score
        }
    }
}

// ------------------------- launch -------------------------------------------
extern "C" void kernel_launch(void* const* d_in, const int* in_sizes, int n_in,
                              void* d_out, int out_size) {
    const float* ref = (const float*)d_in[0];
    const float* src = (const float*)d_in[1];
    const int D = DK;
    const int N = in_sizes[0] / D;
    const int M = in_sizes[1] / D;
    float* out = (float*)d_out;

    cudaFuncSetAttribute(k_gemm_mma, cudaFuncAttributeMaxDynamicSharedMemorySize, DYN_SMEM);

    k_zero<<<16, 256>>>();
    k_split<<<(N * D) / 256, 256>>>(ref, src);

    dim3 gg(M / 128, N / 128);
    k_gemm_mma<<<gg, 256, DYN_SMEM>>>(M);

    k_sums<<<32, 256>>>();

    k_score_hist1<<<N / 4, 256>>>(N, M);
    k_findb1<<<1, 256>>>();
    k_hist2<<<N / 4, 256>>>(N, M);
    k_findb2<<<1, 256>>>();
    k_compact<<<N / 4, 256>>>(N, M);
    k_final<<<1, 1024>>>(out, M);
}